// round 11
// baseline (speedup 1.0000x reference)
#include <cuda_runtime.h>
#include <cuda_fp16.h>
#include <cstdint>

// Problem constants
#define NB    2
#define NS    2048
#define ND    2048
#define NH    16
#define NKVH  4
#define NDH   128
#define NROWS (NB * NS)        // 4096
#define NQKV  3072             // 2048 q + 512 k + 512 v

// fp16 scratch (static device globals: allocation-free)
__device__ __half g_xh   [(size_t)NROWS * ND];    // 16 MB
__device__ __half g_wqkvh[(size_t)NQKV * ND];     // 12 MB  (wq | wk | wv rows)
__device__ __half g_woh  [(size_t)ND * ND];       //  8 MB
__device__ __half g_qkvh [(size_t)NROWS * NQKV];  // 24 MB  row: [q 2048 | k 512 | v 512]
__device__ __half g_oh   [(size_t)NROWS * ND];    // 16 MB

// ---------------------------------------------------------------------------
// PTX helpers
// ---------------------------------------------------------------------------
#define MMA16816(d, a0, a1, a2, a3, b0, b1)                                  \
    asm volatile(                                                            \
        "mma.sync.aligned.m16n8k16.row.col.f32.f16.f16.f32 "                 \
        "{%0,%1,%2,%3}, {%4,%5,%6,%7}, {%8,%9}, {%0,%1,%2,%3};"              \
        : "+f"((d)[0]), "+f"((d)[1]), "+f"((d)[2]), "+f"((d)[3])             \
        : "r"(a0), "r"(a1), "r"(a2), "r"(a3), "r"(b0), "r"(b1))

#define CP_ASYNC16(dst, src)                                                 \
    asm volatile("cp.async.cg.shared.global [%0], [%1], 16;" ::              \
                 "r"(dst), "l"(src))
#define CP_COMMIT() asm volatile("cp.async.commit_group;")
#define CP_WAIT0()  asm volatile("cp.async.wait_group 0;" ::: "memory")
#define CP_WAIT1()  asm volatile("cp.async.wait_group 1;" ::: "memory")

#define LDSM_X4(r0, r1, r2, r3, a)                                           \
    asm volatile("ldmatrix.sync.aligned.m8n8.x4.shared.b16 "                 \
                 "{%0,%1,%2,%3}, [%4];"                                      \
                 : "=r"(r0), "=r"(r1), "=r"(r2), "=r"(r3) : "r"(a))
#define LDSM_X4T(r0, r1, r2, r3, a)                                          \
    asm volatile("ldmatrix.sync.aligned.m8n8.x4.trans.shared.b16 "           \
                 "{%0,%1,%2,%3}, [%4];"                                      \
                 : "=r"(r0), "=r"(r1), "=r"(r2), "=r"(r3) : "r"(a))

__device__ __forceinline__ uint32_t s2u(const void* p) {
    return (uint32_t)__cvta_generic_to_shared(p);
}

// ---------------------------------------------------------------------------
// float -> half conversion
// ---------------------------------------------------------------------------
__global__ void f2h_kernel(const float* __restrict__ in, __half* __restrict__ out,
                           int n4)
{
    int i = blockIdx.x * blockDim.x + threadIdx.x;
    if (i < n4) {
        float4 v = ((const float4*)in)[i];
        __half2* o = (__half2*)out + i * 2;
        o[0] = __floats2half2_rn(v.x, v.y);
        o[1] = __floats2half2_rn(v.z, v.w);
    }
}

// ---------------------------------------------------------------------------
// HGEMM: C[M,N] = A[M,K](half,row) @ W[N,K](half,row)^T, fp32 accum.
// CTA tile 256x128 (halves B-side L2 traffic vs 128x128), BK=32,
// 256 threads (8 warps in 4x2, warp tile 64x64), 3-stage cp.async ring,
// ldmatrix fragment loads.
// ---------------------------------------------------------------------------
#define SKP 40
#define GEMM_SMEM (3 * (256 + 128) * SKP * 2)   // 92160 B

template <bool HALF_OUT>
__global__ __launch_bounds__(256)
void hgemm_nt(const __half* __restrict__ A, const __half* __restrict__ W,
              void* __restrict__ Cout, int M, int N, int K)
{
    extern __shared__ __half hsm[];
    __half (*As)[256][SKP] = (__half(*)[256][SKP])hsm;
    __half (*Bs)[128][SKP] = (__half(*)[128][SKP])(hsm + 3 * 256 * SKP);

    const int m0 = blockIdx.y * 256;
    const int n0 = blockIdx.x * 128;
    const int t  = threadIdx.x;
    const int lane = t & 31, wid = t >> 5;
    const int wm = (wid & 3) * 64;       // 4 warp rows
    const int wn = (wid >> 2) * 64;      // 2 warp cols
    const int g  = lane >> 2;
    const int c  = (lane & 3) * 2;
    const int l15 = lane & 15, l16 = (lane >> 4) * 8;

    float acc[4][8][4];
#pragma unroll
    for (int mt = 0; mt < 4; ++mt)
#pragma unroll
        for (int nb = 0; nb < 8; ++nb)
#pragma unroll
            for (int i = 0; i < 4; ++i) acc[mt][nb][i] = 0.0f;

    const int lr = t >> 2, lseg = (t & 3) * 8;

    auto load_tile = [&](int buf, int k0) {
#pragma unroll
        for (int it = 0; it < 4; ++it) {          // A: 256 rows
            const int row = lr + it * 64;
            CP_ASYNC16(s2u(&As[buf][row][lseg]),
                       A + (size_t)(m0 + row) * K + k0 + lseg);
        }
#pragma unroll
        for (int it = 0; it < 2; ++it) {          // B: 128 rows
            const int row = lr + it * 64;
            CP_ASYNC16(s2u(&Bs[buf][row][lseg]),
                       W + (size_t)(n0 + row) * K + k0 + lseg);
        }
    };

    const int NSTG = K / 32;
    load_tile(0, 0);  CP_COMMIT();
    load_tile(1, 32); CP_COMMIT();

    for (int s = 0; s < NSTG; ++s) {
        CP_WAIT1();
        __syncthreads();
        if (s + 2 < NSTG) load_tile((s + 2) % 3, (s + 2) * 32);
        CP_COMMIT();
        const int buf = s % 3;

#pragma unroll
        for (int kc = 0; kc < 32; kc += 16) {
            uint32_t a[4][4], b[4][4];
#pragma unroll
            for (int mt = 0; mt < 4; ++mt)
                LDSM_X4(a[mt][0], a[mt][1], a[mt][2], a[mt][3],
                        s2u(&As[buf][wm + mt * 16 + l15][kc + l16]));
#pragma unroll
            for (int nt = 0; nt < 4; ++nt)
                LDSM_X4(b[nt][0], b[nt][1], b[nt][2], b[nt][3],
                        s2u(&Bs[buf][wn + nt * 16 + l15][kc + l16]));
            // b[nt][0]=b0(n), b[nt][1]=b0(n+8), b[nt][2]=b1(n), b[nt][3]=b1(n+8)
#pragma unroll
            for (int mt = 0; mt < 4; ++mt)
#pragma unroll
                for (int nb = 0; nb < 8; ++nb)
                    MMA16816(acc[mt][nb],
                             a[mt][0], a[mt][1], a[mt][2], a[mt][3],
                             b[nb >> 1][nb & 1], b[nb >> 1][2 + (nb & 1)]);
        }
    }

    // epilogue
#pragma unroll
    for (int mt = 0; mt < 4; ++mt) {
#pragma unroll
        for (int nb = 0; nb < 8; ++nb) {
            const size_t row = (size_t)(m0 + wm + mt * 16 + g);
            const int col = n0 + wn + nb * 8 + c;
            if (HALF_OUT) {
                __half* C = (__half*)Cout;
                *(__half2*)&C[row * N + col] =
                    __floats2half2_rn(acc[mt][nb][0], acc[mt][nb][1]);
                *(__half2*)&C[(row + 8) * N + col] =
                    __floats2half2_rn(acc[mt][nb][2], acc[mt][nb][3]);
            } else {
                float* C = (float*)Cout;
                *(float2*)&C[row * N + col] =
                    make_float2(acc[mt][nb][0], acc[mt][nb][1]);
                *(float2*)&C[(row + 8) * N + col] =
                    make_float2(acc[mt][nb][2], acc[mt][nb][3]);
            }
        }
    }
}

// ---------------------------------------------------------------------------
// RoPE on fused qkv buffer (fp32 math).
// Folds (1/sqrt(Dh)) * log2(e) into q so attention can use exp2.
// ---------------------------------------------------------------------------
__global__ void rope_h_kernel(const float* __restrict__ fc,
                              const float* __restrict__ fs)
{
    int idx = blockIdx.x * blockDim.x + threadIdx.x;
    const int QP = NROWS * NH * 64;
    const int KP = NROWS * NKVH * 64;
    __half2* qkv = (__half2*)g_qkvh;   // row stride 1536 half2

    __half2* p;
    int s, i;
    bool isq;
    if (idx < QP) {
        i = idx & 63;
        const int rh = idx >> 6;
        const int row = rh >> 4, h = rh & 15;
        s = row & (NS - 1);
        p = qkv + (size_t)row * 1536 + h * 64 + i;
        isq = true;
    } else if (idx < QP + KP) {
        idx -= QP;
        i = idx & 63;
        const int rh = idx >> 6;
        const int row = rh >> 2, kvh = rh & 3;
        s = row & (NS - 1);
        p = qkv + (size_t)row * 1536 + 1024 + kvh * 64 + i;
        isq = false;
    } else {
        return;
    }

    const float cs = fc[s * 64 + i];
    const float sn = fs[s * 64 + i];
    float2 v = __half22float2(*p);
    float orr = v.x * cs - v.y * sn;
    float oii = v.x * sn + v.y * cs;
    if (isq) {
        const float qscale = 0.08838834764831845f * 1.4426950408889634f;
        orr *= qscale; oii *= qscale;
    }
    *p = __floats2half2_rn(orr, oii);
}

// ---------------------------------------------------------------------------
// Flash attention: 128 q-rows x 64 kv-cols per CTA, 8 warps, Dh=128.
// Q fragments hoisted; K/V fragments via ldmatrix (trans for V);
// cp.async double-buffered KV tiles. Base-2 fp16x2 softmax (h2exp2 outputs
// ARE the PV A-fragments); fp32 max/accum.
// ---------------------------------------------------------------------------
#define VP 136
#define ATTN_SMEM ((128 + 4 * 64) * VP * 2)   // 104448 B

__global__ __launch_bounds__(256)
void attn_h_kernel()
{
    extern __shared__ __half sm[];
    __half (*Qs)[VP]     = (__half(*)[VP])sm;                      // [128][VP]
    __half (*Ks)[64][VP] = (__half(*)[64][VP])(sm + 128 * VP);     // [2][64][VP]
    __half (*Vs)[64][VP] = (__half(*)[64][VP])(sm + 256 * VP);     // [2][64][VP]

    const int qb = (int)gridDim.x - 1 - (int)blockIdx.x;  // big tiles first
    const int h  = blockIdx.y;
    const int b  = blockIdx.z;
    const int kvh = h >> 2;

    const int t = threadIdx.x;
    const int lane = t & 31, w = t >> 5;
    const int g = lane >> 2;
    const int c = (lane & 3) * 2;
    const int l15 = lane & 15, l16 = (lane >> 4) * 8;

    const __half* qkv = g_qkvh;

    auto load_kv = [&](int buf, int jb) {
#pragma unroll
        for (int it = 0; it < 4; ++it) {
            const int i = t + it * 256;
            const int row = i >> 4, seg = (i & 15) * 8;
            const size_t grow = (size_t)(b * NS + jb * 64 + row) * NQKV + kvh * NDH + seg;
            CP_ASYNC16(s2u(&Ks[buf][row][seg]), qkv + grow + 2048);
            CP_ASYNC16(s2u(&Vs[buf][row][seg]), qkv + grow + 2560);
        }
    };

    // Q tile (128 rows, head h) + first KV tile
#pragma unroll
    for (int it = 0; it < 8; ++it) {
        const int i = t + it * 256;
        const int row = i >> 4, seg = (i & 15) * 8;
        CP_ASYNC16(s2u(&Qs[row][seg]),
                   qkv + (size_t)(b * NS + qb * 128 + row) * NQKV + h * NDH + seg);
    }
    load_kv(0, 0);
    CP_COMMIT();
    CP_WAIT0();
    __syncthreads();

    // Hoist Q fragments (loop-invariant)
    uint32_t qa[8][4];
#pragma unroll
    for (int kc = 0; kc < 8; ++kc)
        LDSM_X4(qa[kc][0], qa[kc][1], qa[kc][2], qa[kc][3],
                s2u(&Qs[w * 16 + l15][kc * 16 + l16]));

    float of[16][4];
#pragma unroll
    for (int nb = 0; nb < 16; ++nb)
#pragma unroll
        for (int i = 0; i < 4; ++i) of[nb][i] = 0.0f;
    float m_[2] = {-1e30f, -1e30f};
    float l_[2] = {0.0f, 0.0f};

    const int jmax = 2 * qb + 1;
    const int warp_row0 = qb * 128 + w * 16;

    for (int jb = 0; jb <= jmax; ++jb) {
        __syncthreads();   // all warps done with buf (jb-1)&1; buf jb published
        if (jb + 1 <= jmax) load_kv((jb + 1) & 1, jb + 1);
        CP_COMMIT();
        const int buf = jb & 1;

        // ---- S = Q @ K^T (log2e*scale pre-folded into Q) ----
        float sc[8][4];
#pragma unroll
        for (int nb = 0; nb < 8; ++nb)
#pragma unroll
            for (int i = 0; i < 4; ++i) sc[nb][i] = 0.0f;

#pragma unroll
        for (int kc = 0; kc < 8; ++kc) {
#pragma unroll
            for (int nt = 0; nt < 4; ++nt) {
                uint32_t k0, k1, k2, k3;
                LDSM_X4(k0, k1, k2, k3,
                        s2u(&Ks[buf][nt * 16 + l15][kc * 16 + l16]));
                MMA16816(sc[nt * 2],     qa[kc][0], qa[kc][1], qa[kc][2], qa[kc][3], k0, k2);
                MMA16816(sc[nt * 2 + 1], qa[kc][0], qa[kc][1], qa[kc][2], qa[kc][3], k1, k3);
            }
        }

        // ---- mask + row max (fp32) ----
        const bool needmask = (jb * 64 + 63 > warp_row0);
        float mn[2], alpha[2];
#pragma unroll
        for (int rr = 0; rr < 2; ++rr) {
            const int rowg = warp_row0 + g + rr * 8;
            float tm = -1e30f;
#pragma unroll
            for (int nb = 0; nb < 8; ++nb) {
                float s0 = sc[nb][rr * 2], s1 = sc[nb][rr * 2 + 1];
                if (needmask) {
                    const int colg = jb * 64 + nb * 8 + c;
                    if (colg > rowg)     s0 = -1e30f;
                    if (colg + 1 > rowg) s1 = -1e30f;
                    sc[nb][rr * 2] = s0; sc[nb][rr * 2 + 1] = s1;
                }
                tm = fmaxf(tm, fmaxf(s0, s1));
            }
            tm = fmaxf(tm, __shfl_xor_sync(0xffffffffu, tm, 1));
            tm = fmaxf(tm, __shfl_xor_sync(0xffffffffu, tm, 2));
            mn[rr] = fmaxf(m_[rr], tm);
            alpha[rr] = exp2f(m_[rr] - mn[rr]);
            m_[rr] = mn[rr];
        }

        // ---- p = 2^(s-m) in fp16x2; outputs are PV A-fragments directly ----
        uint32_t pa[4][4];
        float sum0 = 0.0f, sum1 = 0.0f;
#pragma unroll
        for (int nb = 0; nb < 8; ++nb) {
            __half2 e0 = h2exp2(__floats2half2_rn(sc[nb][0] - mn[0],
                                                  sc[nb][1] - mn[0]));
            __half2 e1 = h2exp2(__floats2half2_rn(sc[nb][2] - mn[1],
                                                  sc[nb][3] - mn[1]));
            pa[nb >> 1][(nb & 1) ? 2 : 0] = *(uint32_t*)&e0;
            pa[nb >> 1][(nb & 1) ? 3 : 1] = *(uint32_t*)&e1;
            float2 f0 = __half22float2(e0);
            float2 f1 = __half22float2(e1);
            sum0 += f0.x + f0.y;
            sum1 += f1.x + f1.y;
        }
        sum0 += __shfl_xor_sync(0xffffffffu, sum0, 1);
        sum0 += __shfl_xor_sync(0xffffffffu, sum0, 2);
        sum1 += __shfl_xor_sync(0xffffffffu, sum1, 1);
        sum1 += __shfl_xor_sync(0xffffffffu, sum1, 2);
        l_[0] = l_[0] * alpha[0] + sum0;
        l_[1] = l_[1] * alpha[1] + sum1;
#pragma unroll
        for (int nb = 0; nb < 16; ++nb) {
            of[nb][0] *= alpha[0];
            of[nb][1] *= alpha[0];
            of[nb][2] *= alpha[1];
            of[nb][3] *= alpha[1];
        }

        // ---- O += P @ V ----
#pragma unroll
        for (int k2 = 0; k2 < 4; ++k2) {
#pragma unroll
            for (int nt = 0; nt < 8; ++nt) {
                uint32_t v0, v1, v2, v3;
                LDSM_X4T(v0, v1, v2, v3,
                         s2u(&Vs[buf][k2 * 16 + l15][nt * 16 + l16]));
                MMA16816(of[nt * 2],     pa[k2][0], pa[k2][1], pa[k2][2], pa[k2][3], v0, v1);
                MMA16816(of[nt * 2 + 1], pa[k2][0], pa[k2][1], pa[k2][2], pa[k2][3], v2, v3);
            }
        }

        CP_WAIT0();   // next KV tile landed (overlapped with compute above)
    }

    // epilogue: normalize, write half
    const float inv0 = 1.0f / l_[0];
    const float inv1 = 1.0f / l_[1];
    const size_t row = (size_t)(b * NS + qb * 128 + w * 16 + g);
#pragma unroll
    for (int nb = 0; nb < 16; ++nb) {
        const int col = h * NDH + nb * 8 + c;
        *(__half2*)&g_oh[row * ND + col] =
            __floats2half2_rn(of[nb][0] * inv0, of[nb][1] * inv0);
        *(__half2*)&g_oh[(row + 8) * ND + col] =
            __floats2half2_rn(of[nb][2] * inv1, of[nb][3] * inv1);
    }
}

// ---------------------------------------------------------------------------
extern "C" void kernel_launch(void* const* d_in, const int* in_sizes, int n_in,
                              void* d_out, int out_size)
{
    const float* x  = (const float*)d_in[0];
    const float* fc = (const float*)d_in[1];
    const float* fs = (const float*)d_in[2];
    const float* wq = (const float*)d_in[3];
    const float* wk = (const float*)d_in[4];
    const float* wv = (const float*)d_in[5];
    const float* wo = (const float*)d_in[6];
    float* out = (float*)d_out;

    __half *xh, *wqkvh, *woh, *qkvh, *oh;
    cudaGetSymbolAddress((void**)&xh,    g_xh);
    cudaGetSymbolAddress((void**)&wqkvh, g_wqkvh);
    cudaGetSymbolAddress((void**)&woh,   g_woh);
    cudaGetSymbolAddress((void**)&qkvh,  g_qkvh);
    cudaGetSymbolAddress((void**)&oh,    g_oh);

    // fp32 -> fp16 conversions (wq|wk|wv concatenated into g_wqkvh)
    const int nx  = NROWS * ND / 4;
    const int nwq = ND * ND / 4;
    const int nkv = 512 * 2048 / 4;
    f2h_kernel<<<(nx  + 255) / 256, 256>>>(x,  xh, nx);
    f2h_kernel<<<(nwq + 255) / 256, 256>>>(wq, wqkvh, nwq);
    f2h_kernel<<<(nkv + 255) / 256, 256>>>(wk, wqkvh + (size_t)2048 * 2048, nkv);
    f2h_kernel<<<(nkv + 255) / 256, 256>>>(wv, wqkvh + (size_t)2560 * 2048, nkv);
    f2h_kernel<<<(nwq + 255) / 256, 256>>>(wo, woh, nwq);

    // Fused QKV projection: [4096,2048] @ [3072,2048]^T -> [4096,3072] half
    cudaFuncSetAttribute(hgemm_nt<true>,
                         cudaFuncAttributeMaxDynamicSharedMemorySize, GEMM_SMEM);
    cudaFuncSetAttribute(hgemm_nt<false>,
                         cudaFuncAttributeMaxDynamicSharedMemorySize, GEMM_SMEM);
    hgemm_nt<true><<<dim3(NQKV / 128, NROWS / 256), 256, GEMM_SMEM>>>(
        xh, wqkvh, qkvh, NROWS, NQKV, ND);

    // RoPE (q pre-scaled by log2e/sqrt(Dh))
    const int total_pairs = NROWS * (NH + NKVH) * 64;
    rope_h_kernel<<<(total_pairs + 255) / 256, 256>>>(fc, fs);

    // Causal GQA flash attention
    cudaFuncSetAttribute(attn_h_kernel,
                         cudaFuncAttributeMaxDynamicSharedMemorySize, ATTN_SMEM);
    attn_h_kernel<<<dim3(NS / 128, NH, NB), 256, ATTN_SMEM>>>();

    // Output projection (fp32 output)
    hgemm_nt<false><<<dim3(ND / 128, NROWS / 256), 256, GEMM_SMEM>>>(
        oh, woh, out, NROWS, ND, ND);
}

// round 12
// speedup vs baseline: 1.0539x; 1.0539x over previous
#include <cuda_runtime.h>
#include <cuda_fp16.h>
#include <cstdint>

// Problem constants
#define NB    2
#define NS    2048
#define ND    2048
#define NH    16
#define NKVH  4
#define NDH   128
#define NROWS (NB * NS)        // 4096
#define NQKV  3072             // 2048 q + 512 k + 512 v

// fp16 scratch (static device globals: allocation-free)
__device__ __half g_xh   [(size_t)NROWS * ND];    // 16 MB
__device__ __half g_wqkvh[(size_t)NQKV * ND];     // 12 MB  (wq | wk | wv rows)
__device__ __half g_woh  [(size_t)ND * ND];       //  8 MB
__device__ __half g_qkvh [(size_t)NROWS * NQKV];  // 24 MB  row: [q 2048 | k 512 | v 512]
__device__ __half g_oh   [(size_t)NROWS * ND];    // 16 MB

// ---------------------------------------------------------------------------
// PTX helpers
// ---------------------------------------------------------------------------
#define MMA16816(d, a0, a1, a2, a3, b0, b1)                                  \
    asm volatile(                                                            \
        "mma.sync.aligned.m16n8k16.row.col.f32.f16.f16.f32 "                 \
        "{%0,%1,%2,%3}, {%4,%5,%6,%7}, {%8,%9}, {%0,%1,%2,%3};"              \
        : "+f"((d)[0]), "+f"((d)[1]), "+f"((d)[2]), "+f"((d)[3])             \
        : "r"(a0), "r"(a1), "r"(a2), "r"(a3), "r"(b0), "r"(b1))

#define CP_ASYNC16(dst, src)                                                 \
    asm volatile("cp.async.cg.shared.global [%0], [%1], 16;" ::              \
                 "r"(dst), "l"(src))
#define CP_COMMIT() asm volatile("cp.async.commit_group;")
#define CP_WAIT0()  asm volatile("cp.async.wait_group 0;" ::: "memory")
#define CP_WAIT1()  asm volatile("cp.async.wait_group 1;" ::: "memory")

#define LDSM_X4(r0, r1, r2, r3, a)                                           \
    asm volatile("ldmatrix.sync.aligned.m8n8.x4.shared.b16 "                 \
                 "{%0,%1,%2,%3}, [%4];"                                      \
                 : "=r"(r0), "=r"(r1), "=r"(r2), "=r"(r3) : "r"(a))
#define LDSM_X4T(r0, r1, r2, r3, a)                                          \
    asm volatile("ldmatrix.sync.aligned.m8n8.x4.trans.shared.b16 "           \
                 "{%0,%1,%2,%3}, [%4];"                                      \
                 : "=r"(r0), "=r"(r1), "=r"(r2), "=r"(r3) : "r"(a))

__device__ __forceinline__ uint32_t s2u(const void* p) {
    return (uint32_t)__cvta_generic_to_shared(p);
}

// ---------------------------------------------------------------------------
// float -> half conversions (x in one launch, all four weights in another,
// so the interesting kernels land inside ncu's -s 5 capture window)
// ---------------------------------------------------------------------------
__global__ void f2h_kernel(const float* __restrict__ in, __half* __restrict__ out,
                           int n4)
{
    int i = blockIdx.x * blockDim.x + threadIdx.x;
    if (i < n4) {
        float4 v = ((const float4*)in)[i];
        __half2* o = (__half2*)out + i * 2;
        o[0] = __floats2half2_rn(v.x, v.y);
        o[1] = __floats2half2_rn(v.z, v.w);
    }
}

__global__ void f2h_w_kernel(const float* __restrict__ wq,
                             const float* __restrict__ wk,
                             const float* __restrict__ wv,
                             const float* __restrict__ wo)
{
    const int NWQ = ND * ND / 4;            // 1048576 float4 groups
    const int NKV = (NKVH * NDH) * ND / 4;  // 262144
    int i = blockIdx.x * blockDim.x + threadIdx.x;

    const float* src;
    __half* dst;
    int off;
    if (i < NWQ) {
        src = wq; dst = g_wqkvh; off = i;
    } else if (i < NWQ + NKV) {
        src = wk; dst = g_wqkvh + (size_t)2048 * 2048; off = i - NWQ;
    } else if (i < NWQ + 2 * NKV) {
        src = wv; dst = g_wqkvh + (size_t)2560 * 2048; off = i - NWQ - NKV;
    } else if (i < 2 * NWQ + 2 * NKV) {
        src = wo; dst = g_woh; off = i - NWQ - 2 * NKV;
    } else {
        return;
    }
    float4 v = ((const float4*)src)[off];
    __half2* o = (__half2*)dst + off * 2;
    o[0] = __floats2half2_rn(v.x, v.y);
    o[1] = __floats2half2_rn(v.z, v.w);
}

// ---------------------------------------------------------------------------
// HGEMM: C[M,N] = A[M,K](half,row) @ W[N,K](half,row)^T, fp32 accum.
// CTA tile 128x128, BK=32, 128 threads (4 warps, warp tile 64x64),
// 3-stage cp.async ring, ldmatrix fragment loads. (Round-10 proven config.)
// ---------------------------------------------------------------------------
#define SKP 40
#define GEMM_SMEM (2 * 3 * 128 * SKP * 2)   // 61440 B

template <bool HALF_OUT>
__global__ __launch_bounds__(128)
void hgemm_nt(const __half* __restrict__ A, const __half* __restrict__ W,
              void* __restrict__ Cout, int M, int N, int K)
{
    extern __shared__ __half hsm[];
    __half (*As)[128][SKP] = (__half(*)[128][SKP])hsm;
    __half (*Bs)[128][SKP] = (__half(*)[128][SKP])(hsm + 3 * 128 * SKP);

    const int m0 = blockIdx.y * 128;
    const int n0 = blockIdx.x * 128;
    const int t  = threadIdx.x;
    const int lane = t & 31, wid = t >> 5;
    const int wm = (wid & 1) * 64;
    const int wn = (wid >> 1) * 64;
    const int g  = lane >> 2;
    const int c  = (lane & 3) * 2;
    const int l15 = lane & 15, l16 = (lane >> 4) * 8;

    float acc[4][8][4];
#pragma unroll
    for (int mt = 0; mt < 4; ++mt)
#pragma unroll
        for (int nb = 0; nb < 8; ++nb)
#pragma unroll
            for (int i = 0; i < 4; ++i) acc[mt][nb][i] = 0.0f;

    const int lr = t >> 2, lseg = (t & 3) * 8;

    auto load_tile = [&](int buf, int k0) {
#pragma unroll
        for (int it = 0; it < 4; ++it) {
            const int row = lr + it * 32;
            CP_ASYNC16(s2u(&As[buf][row][lseg]),
                       A + (size_t)(m0 + row) * K + k0 + lseg);
            CP_ASYNC16(s2u(&Bs[buf][row][lseg]),
                       W + (size_t)(n0 + row) * K + k0 + lseg);
        }
    };

    const int NSTG = K / 32;
    load_tile(0, 0);  CP_COMMIT();
    load_tile(1, 32); CP_COMMIT();

    for (int s = 0; s < NSTG; ++s) {
        CP_WAIT1();
        __syncthreads();
        if (s + 2 < NSTG) load_tile((s + 2) % 3, (s + 2) * 32);
        CP_COMMIT();
        const int buf = s % 3;

#pragma unroll
        for (int kc = 0; kc < 32; kc += 16) {
            uint32_t a[4][4], b[4][4];
#pragma unroll
            for (int mt = 0; mt < 4; ++mt)
                LDSM_X4(a[mt][0], a[mt][1], a[mt][2], a[mt][3],
                        s2u(&As[buf][wm + mt * 16 + l15][kc + l16]));
#pragma unroll
            for (int nt = 0; nt < 4; ++nt)
                LDSM_X4(b[nt][0], b[nt][1], b[nt][2], b[nt][3],
                        s2u(&Bs[buf][wn + nt * 16 + l15][kc + l16]));
            // b[nt][0]=b0(n), b[nt][1]=b0(n+8), b[nt][2]=b1(n), b[nt][3]=b1(n+8)
#pragma unroll
            for (int mt = 0; mt < 4; ++mt)
#pragma unroll
                for (int nb = 0; nb < 8; ++nb)
                    MMA16816(acc[mt][nb],
                             a[mt][0], a[mt][1], a[mt][2], a[mt][3],
                             b[nb >> 1][nb & 1], b[nb >> 1][2 + (nb & 1)]);
        }
    }

    // epilogue
#pragma unroll
    for (int mt = 0; mt < 4; ++mt) {
#pragma unroll
        for (int nb = 0; nb < 8; ++nb) {
            const size_t row = (size_t)(m0 + wm + mt * 16 + g);
            const int col = n0 + wn + nb * 8 + c;
            if (HALF_OUT) {
                __half* C = (__half*)Cout;
                *(__half2*)&C[row * N + col] =
                    __floats2half2_rn(acc[mt][nb][0], acc[mt][nb][1]);
                *(__half2*)&C[(row + 8) * N + col] =
                    __floats2half2_rn(acc[mt][nb][2], acc[mt][nb][3]);
            } else {
                float* C = (float*)Cout;
                *(float2*)&C[row * N + col] =
                    make_float2(acc[mt][nb][0], acc[mt][nb][1]);
                *(float2*)&C[(row + 8) * N + col] =
                    make_float2(acc[mt][nb][2], acc[mt][nb][3]);
            }
        }
    }
}

// ---------------------------------------------------------------------------
// RoPE on fused qkv buffer (fp32 math).
// Folds (1/sqrt(Dh)) * log2(e) into q so attention can use exp2.
// ---------------------------------------------------------------------------
__global__ void rope_h_kernel(const float* __restrict__ fc,
                              const float* __restrict__ fs)
{
    int idx = blockIdx.x * blockDim.x + threadIdx.x;
    const int QP = NROWS * NH * 64;
    const int KP = NROWS * NKVH * 64;
    __half2* qkv = (__half2*)g_qkvh;   // row stride 1536 half2

    __half2* p;
    int s, i;
    bool isq;
    if (idx < QP) {
        i = idx & 63;
        const int rh = idx >> 6;
        const int row = rh >> 4, h = rh & 15;
        s = row & (NS - 1);
        p = qkv + (size_t)row * 1536 + h * 64 + i;
        isq = true;
    } else if (idx < QP + KP) {
        idx -= QP;
        i = idx & 63;
        const int rh = idx >> 6;
        const int row = rh >> 2, kvh = rh & 3;
        s = row & (NS - 1);
        p = qkv + (size_t)row * 1536 + 1024 + kvh * 64 + i;
        isq = false;
    } else {
        return;
    }

    const float cs = fc[s * 64 + i];
    const float sn = fs[s * 64 + i];
    float2 v = __half22float2(*p);
    float orr = v.x * cs - v.y * sn;
    float oii = v.x * sn + v.y * cs;
    if (isq) {
        const float qscale = 0.08838834764831845f * 1.4426950408889634f;
        orr *= qscale; oii *= qscale;
    }
    *p = __floats2half2_rn(orr, oii);
}

// ---------------------------------------------------------------------------
// Flash attention: 128 q-rows x 64 kv-cols per CTA, 8 warps, Dh=128.
// Q fragments hoisted; K/V fragments via ldmatrix (trans for V);
// cp.async double-buffered KV tiles. Base-2 fp16x2 softmax (h2exp2 outputs
// ARE the PV A-fragments); fp32 max/accum.
// ---------------------------------------------------------------------------
#define VP 136
#define ATTN_SMEM ((128 + 4 * 64) * VP * 2)   // 104448 B

__global__ __launch_bounds__(256)
void attn_h_kernel()
{
    extern __shared__ __half sm[];
    __half (*Qs)[VP]     = (__half(*)[VP])sm;                      // [128][VP]
    __half (*Ks)[64][VP] = (__half(*)[64][VP])(sm + 128 * VP);     // [2][64][VP]
    __half (*Vs)[64][VP] = (__half(*)[64][VP])(sm + 256 * VP);     // [2][64][VP]

    const int qb = (int)gridDim.x - 1 - (int)blockIdx.x;  // big tiles first
    const int h  = blockIdx.y;
    const int b  = blockIdx.z;
    const int kvh = h >> 2;

    const int t = threadIdx.x;
    const int lane = t & 31, w = t >> 5;
    const int g = lane >> 2;
    const int c = (lane & 3) * 2;
    const int l15 = lane & 15, l16 = (lane >> 4) * 8;

    const __half* qkv = g_qkvh;

    auto load_kv = [&](int buf, int jb) {
#pragma unroll
        for (int it = 0; it < 4; ++it) {
            const int i = t + it * 256;
            const int row = i >> 4, seg = (i & 15) * 8;
            const size_t grow = (size_t)(b * NS + jb * 64 + row) * NQKV + kvh * NDH + seg;
            CP_ASYNC16(s2u(&Ks[buf][row][seg]), qkv + grow + 2048);
            CP_ASYNC16(s2u(&Vs[buf][row][seg]), qkv + grow + 2560);
        }
    };

    // Q tile (128 rows, head h) + first KV tile
#pragma unroll
    for (int it = 0; it < 8; ++it) {
        const int i = t + it * 256;
        const int row = i >> 4, seg = (i & 15) * 8;
        CP_ASYNC16(s2u(&Qs[row][seg]),
                   qkv + (size_t)(b * NS + qb * 128 + row) * NQKV + h * NDH + seg);
    }
    load_kv(0, 0);
    CP_COMMIT();
    CP_WAIT0();
    __syncthreads();

    // Hoist Q fragments (loop-invariant)
    uint32_t qa[8][4];
#pragma unroll
    for (int kc = 0; kc < 8; ++kc)
        LDSM_X4(qa[kc][0], qa[kc][1], qa[kc][2], qa[kc][3],
                s2u(&Qs[w * 16 + l15][kc * 16 + l16]));

    float of[16][4];
#pragma unroll
    for (int nb = 0; nb < 16; ++nb)
#pragma unroll
        for (int i = 0; i < 4; ++i) of[nb][i] = 0.0f;
    float m_[2] = {-1e30f, -1e30f};
    float l_[2] = {0.0f, 0.0f};

    const int jmax = 2 * qb + 1;
    const int warp_row0 = qb * 128 + w * 16;

    for (int jb = 0; jb <= jmax; ++jb) {
        __syncthreads();   // all warps done with buf (jb-1)&1; buf jb published
        if (jb + 1 <= jmax) load_kv((jb + 1) & 1, jb + 1);
        CP_COMMIT();
        const int buf = jb & 1;

        // ---- S = Q @ K^T (log2e*scale pre-folded into Q) ----
        float sc[8][4];
#pragma unroll
        for (int nb = 0; nb < 8; ++nb)
#pragma unroll
            for (int i = 0; i < 4; ++i) sc[nb][i] = 0.0f;

#pragma unroll
        for (int kc = 0; kc < 8; ++kc) {
#pragma unroll
            for (int nt = 0; nt < 4; ++nt) {
                uint32_t k0, k1, k2, k3;
                LDSM_X4(k0, k1, k2, k3,
                        s2u(&Ks[buf][nt * 16 + l15][kc * 16 + l16]));
                MMA16816(sc[nt * 2],     qa[kc][0], qa[kc][1], qa[kc][2], qa[kc][3], k0, k2);
                MMA16816(sc[nt * 2 + 1], qa[kc][0], qa[kc][1], qa[kc][2], qa[kc][3], k1, k3);
            }
        }

        // ---- mask + row max (fp32) ----
        const bool needmask = (jb * 64 + 63 > warp_row0);
        float mn[2], alpha[2];
#pragma unroll
        for (int rr = 0; rr < 2; ++rr) {
            const int rowg = warp_row0 + g + rr * 8;
            float tm = -1e30f;
#pragma unroll
            for (int nb = 0; nb < 8; ++nb) {
                float s0 = sc[nb][rr * 2], s1 = sc[nb][rr * 2 + 1];
                if (needmask) {
                    const int colg = jb * 64 + nb * 8 + c;
                    if (colg > rowg)     s0 = -1e30f;
                    if (colg + 1 > rowg) s1 = -1e30f;
                    sc[nb][rr * 2] = s0; sc[nb][rr * 2 + 1] = s1;
                }
                tm = fmaxf(tm, fmaxf(s0, s1));
            }
            tm = fmaxf(tm, __shfl_xor_sync(0xffffffffu, tm, 1));
            tm = fmaxf(tm, __shfl_xor_sync(0xffffffffu, tm, 2));
            mn[rr] = fmaxf(m_[rr], tm);
            alpha[rr] = exp2f(m_[rr] - mn[rr]);
            m_[rr] = mn[rr];
        }

        // ---- p = 2^(s-m) in fp16x2; outputs are PV A-fragments directly ----
        uint32_t pa[4][4];
        float sum0 = 0.0f, sum1 = 0.0f;
#pragma unroll
        for (int nb = 0; nb < 8; ++nb) {
            __half2 e0 = h2exp2(__floats2half2_rn(sc[nb][0] - mn[0],
                                                  sc[nb][1] - mn[0]));
            __half2 e1 = h2exp2(__floats2half2_rn(sc[nb][2] - mn[1],
                                                  sc[nb][3] - mn[1]));
            pa[nb >> 1][(nb & 1) ? 2 : 0] = *(uint32_t*)&e0;
            pa[nb >> 1][(nb & 1) ? 3 : 1] = *(uint32_t*)&e1;
            float2 f0 = __half22float2(e0);
            float2 f1 = __half22float2(e1);
            sum0 += f0.x + f0.y;
            sum1 += f1.x + f1.y;
        }
        sum0 += __shfl_xor_sync(0xffffffffu, sum0, 1);
        sum0 += __shfl_xor_sync(0xffffffffu, sum0, 2);
        sum1 += __shfl_xor_sync(0xffffffffu, sum1, 1);
        sum1 += __shfl_xor_sync(0xffffffffu, sum1, 2);
        l_[0] = l_[0] * alpha[0] + sum0;
        l_[1] = l_[1] * alpha[1] + sum1;
#pragma unroll
        for (int nb = 0; nb < 16; ++nb) {
            of[nb][0] *= alpha[0];
            of[nb][1] *= alpha[0];
            of[nb][2] *= alpha[1];
            of[nb][3] *= alpha[1];
        }

        // ---- O += P @ V ----
#pragma unroll
        for (int k2 = 0; k2 < 4; ++k2) {
#pragma unroll
            for (int nt = 0; nt < 8; ++nt) {
                uint32_t v0, v1, v2, v3;
                LDSM_X4T(v0, v1, v2, v3,
                         s2u(&Vs[buf][k2 * 16 + l15][nt * 16 + l16]));
                MMA16816(of[nt * 2],     pa[k2][0], pa[k2][1], pa[k2][2], pa[k2][3], v0, v1);
                MMA16816(of[nt * 2 + 1], pa[k2][0], pa[k2][1], pa[k2][2], pa[k2][3], v2, v3);
            }
        }

        CP_WAIT0();   // next KV tile landed (overlapped with compute above)
    }

    // epilogue: normalize, write half
    const float inv0 = 1.0f / l_[0];
    const float inv1 = 1.0f / l_[1];
    const size_t row = (size_t)(b * NS + qb * 128 + w * 16 + g);
#pragma unroll
    for (int nb = 0; nb < 16; ++nb) {
        const int col = h * NDH + nb * 8 + c;
        *(__half2*)&g_oh[row * ND + col] =
            __floats2half2_rn(of[nb][0] * inv0, of[nb][1] * inv0);
        *(__half2*)&g_oh[(row + 8) * ND + col] =
            __floats2half2_rn(of[nb][2] * inv1, of[nb][3] * inv1);
    }
}

// ---------------------------------------------------------------------------
extern "C" void kernel_launch(void* const* d_in, const int* in_sizes, int n_in,
                              void* d_out, int out_size)
{
    const float* x  = (const float*)d_in[0];
    const float* fc = (const float*)d_in[1];
    const float* fs = (const float*)d_in[2];
    const float* wq = (const float*)d_in[3];
    const float* wk = (const float*)d_in[4];
    const float* wv = (const float*)d_in[5];
    const float* wo = (const float*)d_in[6];
    float* out = (float*)d_out;

    __half *xh, *wqkvh, *woh, *qkvh, *oh;
    cudaGetSymbolAddress((void**)&xh,    g_xh);
    cudaGetSymbolAddress((void**)&wqkvh, g_wqkvh);
    cudaGetSymbolAddress((void**)&woh,   g_woh);
    cudaGetSymbolAddress((void**)&qkvh,  g_qkvh);
    cudaGetSymbolAddress((void**)&oh,    g_oh);

    // fp32 -> fp16 conversions: x (launch 1), all weights (launch 2)
    const int nx = NROWS * ND / 4;
    const int nw_total = 2 * (ND * ND / 4) + 2 * ((NKVH * NDH) * ND / 4);
    f2h_kernel<<<(nx + 255) / 256, 256>>>(x, xh, nx);
    f2h_w_kernel<<<(nw_total + 255) / 256, 256>>>(wq, wk, wv, wo);

    // Fused QKV projection: [4096,2048] @ [3072,2048]^T -> [4096,3072] half
    cudaFuncSetAttribute(hgemm_nt<true>,
                         cudaFuncAttributeMaxDynamicSharedMemorySize, GEMM_SMEM);
    cudaFuncSetAttribute(hgemm_nt<false>,
                         cudaFuncAttributeMaxDynamicSharedMemorySize, GEMM_SMEM);
    hgemm_nt<true><<<dim3(NQKV / 128, NROWS / 128), 128, GEMM_SMEM>>>(
        xh, wqkvh, qkvh, NROWS, NQKV, ND);

    // RoPE (q pre-scaled by log2e/sqrt(Dh))
    const int total_pairs = NROWS * (NH + NKVH) * 64;
    rope_h_kernel<<<(total_pairs + 255) / 256, 256>>>(fc, fs);

    // Causal GQA flash attention
    cudaFuncSetAttribute(attn_h_kernel,
                         cudaFuncAttributeMaxDynamicSharedMemorySize, ATTN_SMEM);
    attn_h_kernel<<<dim3(NS / 128, NH, NB), 256, ATTN_SMEM>>>();

    // Output projection (fp32 output)
    hgemm_nt<false><<<dim3(ND / 128, NROWS / 128), 128, GEMM_SMEM>>>(
        oh, woh, out, NROWS, ND, ND);
}

// round 13
// speedup vs baseline: 1.0639x; 1.0095x over previous
#include <cuda_runtime.h>
#include <cuda_fp16.h>
#include <cstdint>

// Problem constants
#define NB    2
#define NS    2048
#define ND    2048
#define NH    16
#define NKVH  4
#define NDH   128
#define NROWS (NB * NS)        // 4096
#define NQKV  3072             // 2048 q + 512 k + 512 v

// fp16 scratch (static device globals: allocation-free)
__device__ __half g_xh   [(size_t)NROWS * ND];    // 16 MB
__device__ __half g_wqkvh[(size_t)NQKV * ND];     // 12 MB  (wq | wk | wv rows)
__device__ __half g_woh  [(size_t)ND * ND];       //  8 MB
__device__ __half g_qkvh [(size_t)NROWS * NQKV];  // 24 MB  row: [q 2048 | k 512 | v 512]
__device__ __half g_oh   [(size_t)NROWS * ND];    // 16 MB

// ---------------------------------------------------------------------------
// PTX helpers
// ---------------------------------------------------------------------------
#define MMA16816(d, a0, a1, a2, a3, b0, b1)                                  \
    asm volatile(                                                            \
        "mma.sync.aligned.m16n8k16.row.col.f32.f16.f16.f32 "                 \
        "{%0,%1,%2,%3}, {%4,%5,%6,%7}, {%8,%9}, {%0,%1,%2,%3};"              \
        : "+f"((d)[0]), "+f"((d)[1]), "+f"((d)[2]), "+f"((d)[3])             \
        : "r"(a0), "r"(a1), "r"(a2), "r"(a3), "r"(b0), "r"(b1))

#define CP_ASYNC16(dst, src)                                                 \
    asm volatile("cp.async.cg.shared.global [%0], [%1], 16;" ::              \
                 "r"(dst), "l"(src))
#define CP_COMMIT() asm volatile("cp.async.commit_group;")
#define CP_WAIT0()  asm volatile("cp.async.wait_group 0;" ::: "memory")
#define CP_WAIT1()  asm volatile("cp.async.wait_group 1;" ::: "memory")

#define LDSM_X4(r0, r1, r2, r3, a)                                           \
    asm volatile("ldmatrix.sync.aligned.m8n8.x4.shared.b16 "                 \
                 "{%0,%1,%2,%3}, [%4];"                                      \
                 : "=r"(r0), "=r"(r1), "=r"(r2), "=r"(r3) : "r"(a))
#define LDSM_X4T(r0, r1, r2, r3, a)                                          \
    asm volatile("ldmatrix.sync.aligned.m8n8.x4.trans.shared.b16 "           \
                 "{%0,%1,%2,%3}, [%4];"                                      \
                 : "=r"(r0), "=r"(r1), "=r"(r2), "=r"(r3) : "r"(a))

__device__ __forceinline__ uint32_t s2u(const void* p) {
    return (uint32_t)__cvta_generic_to_shared(p);
}

// ---------------------------------------------------------------------------
// float -> half conversions
// ---------------------------------------------------------------------------
__global__ void f2h_kernel(const float* __restrict__ in, __half* __restrict__ out,
                           int n4)
{
    int i = blockIdx.x * blockDim.x + threadIdx.x;
    if (i < n4) {
        float4 v = ((const float4*)in)[i];
        __half2* o = (__half2*)out + i * 2;
        o[0] = __floats2half2_rn(v.x, v.y);
        o[1] = __floats2half2_rn(v.z, v.w);
    }
}

__global__ void f2h_w_kernel(const float* __restrict__ wq,
                             const float* __restrict__ wk,
                             const float* __restrict__ wv,
                             const float* __restrict__ wo)
{
    const int NWQ = ND * ND / 4;            // 1048576 float4 groups
    const int NKV = (NKVH * NDH) * ND / 4;  // 262144
    int i = blockIdx.x * blockDim.x + threadIdx.x;

    const float* src;
    __half* dst;
    int off;
    if (i < NWQ) {
        src = wq; dst = g_wqkvh; off = i;
    } else if (i < NWQ + NKV) {
        src = wk; dst = g_wqkvh + (size_t)2048 * 2048; off = i - NWQ;
    } else if (i < NWQ + 2 * NKV) {
        src = wv; dst = g_wqkvh + (size_t)2560 * 2048; off = i - NWQ - NKV;
    } else if (i < 2 * NWQ + 2 * NKV) {
        src = wo; dst = g_woh; off = i - NWQ - 2 * NKV;
    } else {
        return;
    }
    float4 v = ((const float4*)src)[off];
    __half2* o = (__half2*)dst + off * 2;
    o[0] = __floats2half2_rn(v.x, v.y);
    o[1] = __floats2half2_rn(v.z, v.w);
}

// ---------------------------------------------------------------------------
// HGEMM: C[M,N] = A[M,K](half,row) @ W[N,K](half,row)^T, fp32 accum.
// CTA tile 128x128, BK=32, 128 threads (4 warps, warp tile 64x64),
// 3-stage cp.async ring, ldmatrix fragment loads.
// MODE: 0 = fp32 out, 1 = half out, 2 = half out + fused RoPE epilogue
//       (for the QKV projection: q cols [0,2048) get rope * log2e/sqrt(Dh),
//        k cols [2048,2560) get rope, v cols [2560,3072) pass through).
// ---------------------------------------------------------------------------
#define SKP 40
#define GEMM_SMEM (2 * 3 * 128 * SKP * 2)   // 61440 B

template <int MODE>
__global__ __launch_bounds__(128)
void hgemm_nt(const __half* __restrict__ A, const __half* __restrict__ W,
              void* __restrict__ Cout, int M, int N, int K,
              const float* __restrict__ fc, const float* __restrict__ fs)
{
    extern __shared__ __half hsm[];
    __half (*As)[128][SKP] = (__half(*)[128][SKP])hsm;
    __half (*Bs)[128][SKP] = (__half(*)[128][SKP])(hsm + 3 * 128 * SKP);

    const int m0 = blockIdx.y * 128;
    const int n0 = blockIdx.x * 128;
    const int t  = threadIdx.x;
    const int lane = t & 31, wid = t >> 5;
    const int wm = (wid & 1) * 64;
    const int wn = (wid >> 1) * 64;
    const int g  = lane >> 2;
    const int c  = (lane & 3) * 2;
    const int l15 = lane & 15, l16 = (lane >> 4) * 8;

    float acc[4][8][4];
#pragma unroll
    for (int mt = 0; mt < 4; ++mt)
#pragma unroll
        for (int nb = 0; nb < 8; ++nb)
#pragma unroll
            for (int i = 0; i < 4; ++i) acc[mt][nb][i] = 0.0f;

    const int lr = t >> 2, lseg = (t & 3) * 8;

    auto load_tile = [&](int buf, int k0) {
#pragma unroll
        for (int it = 0; it < 4; ++it) {
            const int row = lr + it * 32;
            CP_ASYNC16(s2u(&As[buf][row][lseg]),
                       A + (size_t)(m0 + row) * K + k0 + lseg);
            CP_ASYNC16(s2u(&Bs[buf][row][lseg]),
                       W + (size_t)(n0 + row) * K + k0 + lseg);
        }
    };

    const int NSTG = K / 32;
    load_tile(0, 0);  CP_COMMIT();
    load_tile(1, 32); CP_COMMIT();

    for (int s = 0; s < NSTG; ++s) {
        CP_WAIT1();
        __syncthreads();
        if (s + 2 < NSTG) load_tile((s + 2) % 3, (s + 2) * 32);
        CP_COMMIT();
        const int buf = s % 3;

#pragma unroll
        for (int kc = 0; kc < 32; kc += 16) {
            uint32_t a[4][4], b[4][4];
#pragma unroll
            for (int mt = 0; mt < 4; ++mt)
                LDSM_X4(a[mt][0], a[mt][1], a[mt][2], a[mt][3],
                        s2u(&As[buf][wm + mt * 16 + l15][kc + l16]));
#pragma unroll
            for (int nt = 0; nt < 4; ++nt)
                LDSM_X4(b[nt][0], b[nt][1], b[nt][2], b[nt][3],
                        s2u(&Bs[buf][wn + nt * 16 + l15][kc + l16]));
            // b[nt][0]=b0(n), b[nt][1]=b0(n+8), b[nt][2]=b1(n), b[nt][3]=b1(n+8)
#pragma unroll
            for (int mt = 0; mt < 4; ++mt)
#pragma unroll
                for (int nb = 0; nb < 8; ++nb)
                    MMA16816(acc[mt][nb],
                             a[mt][0], a[mt][1], a[mt][2], a[mt][3],
                             b[nb >> 1][nb & 1], b[nb >> 1][2 + (nb & 1)]);
        }
    }

    // epilogue
#pragma unroll
    for (int mt = 0; mt < 4; ++mt) {
#pragma unroll
        for (int nb = 0; nb < 8; ++nb) {
            const size_t row = (size_t)(m0 + wm + mt * 16 + g);
            const int col = n0 + wn + nb * 8 + c;
            if (MODE == 2 && col < 2560) {
                // Fused RoPE: (acc[0],acc[1]) is the (x_r,x_i) pair for `row`,
                // (acc[2],acc[3]) for `row+8`. Pair index within head:
                const int pi = (col & (NDH - 1)) >> 1;
                const int s0 = (int)(row & (NS - 1));
                const int s1 = (int)((row + 8) & (NS - 1));
                const float c0 = fc[s0 * 64 + pi], sn0 = fs[s0 * 64 + pi];
                const float c1 = fc[s1 * 64 + pi], sn1 = fs[s1 * 64 + pi];
                float r0 = acc[mt][nb][0] * c0 - acc[mt][nb][1] * sn0;
                float i0 = acc[mt][nb][0] * sn0 + acc[mt][nb][1] * c0;
                float r1 = acc[mt][nb][2] * c1 - acc[mt][nb][3] * sn1;
                float i1 = acc[mt][nb][2] * sn1 + acc[mt][nb][3] * c1;
                if (col < 2048) {
                    const float qsc = 0.08838834764831845f * 1.4426950408889634f;
                    r0 *= qsc; i0 *= qsc; r1 *= qsc; i1 *= qsc;
                }
                acc[mt][nb][0] = r0; acc[mt][nb][1] = i0;
                acc[mt][nb][2] = r1; acc[mt][nb][3] = i1;
            }
            if (MODE != 0) {
                __half* C = (__half*)Cout;
                *(__half2*)&C[row * N + col] =
                    __floats2half2_rn(acc[mt][nb][0], acc[mt][nb][1]);
                *(__half2*)&C[(row + 8) * N + col] =
                    __floats2half2_rn(acc[mt][nb][2], acc[mt][nb][3]);
            } else {
                float* C = (float*)Cout;
                *(float2*)&C[row * N + col] =
                    make_float2(acc[mt][nb][0], acc[mt][nb][1]);
                *(float2*)&C[(row + 8) * N + col] =
                    make_float2(acc[mt][nb][2], acc[mt][nb][3]);
            }
        }
    }
}

// ---------------------------------------------------------------------------
// Flash attention: 128 q-rows x 64 kv-cols per CTA, 8 warps, Dh=128.
// Q fragments hoisted; K/V fragments via ldmatrix (trans for V);
// cp.async double-buffered KV tiles. Base-2 fp16x2 softmax (h2exp2 outputs
// ARE the PV A-fragments); fp32 max/accum.
// ---------------------------------------------------------------------------
#define VP 136
#define ATTN_SMEM ((128 + 4 * 64) * VP * 2)   // 104448 B

__global__ __launch_bounds__(256)
void attn_h_kernel()
{
    extern __shared__ __half sm[];
    __half (*Qs)[VP]     = (__half(*)[VP])sm;                      // [128][VP]
    __half (*Ks)[64][VP] = (__half(*)[64][VP])(sm + 128 * VP);     // [2][64][VP]
    __half (*Vs)[64][VP] = (__half(*)[64][VP])(sm + 256 * VP);     // [2][64][VP]

    const int qb = (int)gridDim.x - 1 - (int)blockIdx.x;  // big tiles first
    const int h  = blockIdx.y;
    const int b  = blockIdx.z;
    const int kvh = h >> 2;

    const int t = threadIdx.x;
    const int lane = t & 31, w = t >> 5;
    const int g = lane >> 2;
    const int c = (lane & 3) * 2;
    const int l15 = lane & 15, l16 = (lane >> 4) * 8;

    const __half* qkv = g_qkvh;

    auto load_kv = [&](int buf, int jb) {
#pragma unroll
        for (int it = 0; it < 4; ++it) {
            const int i = t + it * 256;
            const int row = i >> 4, seg = (i & 15) * 8;
            const size_t grow = (size_t)(b * NS + jb * 64 + row) * NQKV + kvh * NDH + seg;
            CP_ASYNC16(s2u(&Ks[buf][row][seg]), qkv + grow + 2048);
            CP_ASYNC16(s2u(&Vs[buf][row][seg]), qkv + grow + 2560);
        }
    };

    // Q tile (128 rows, head h) + first KV tile
#pragma unroll
    for (int it = 0; it < 8; ++it) {
        const int i = t + it * 256;
        const int row = i >> 4, seg = (i & 15) * 8;
        CP_ASYNC16(s2u(&Qs[row][seg]),
                   qkv + (size_t)(b * NS + qb * 128 + row) * NQKV + h * NDH + seg);
    }
    load_kv(0, 0);
    CP_COMMIT();
    CP_WAIT0();
    __syncthreads();

    // Hoist Q fragments (loop-invariant)
    uint32_t qa[8][4];
#pragma unroll
    for (int kc = 0; kc < 8; ++kc)
        LDSM_X4(qa[kc][0], qa[kc][1], qa[kc][2], qa[kc][3],
                s2u(&Qs[w * 16 + l15][kc * 16 + l16]));

    float of[16][4];
#pragma unroll
    for (int nb = 0; nb < 16; ++nb)
#pragma unroll
        for (int i = 0; i < 4; ++i) of[nb][i] = 0.0f;
    float m_[2] = {-1e30f, -1e30f};
    float l_[2] = {0.0f, 0.0f};

    const int jmax = 2 * qb + 1;
    const int warp_row0 = qb * 128 + w * 16;

    for (int jb = 0; jb <= jmax; ++jb) {
        __syncthreads();   // all warps done with buf (jb-1)&1; buf jb published
        if (jb + 1 <= jmax) load_kv((jb + 1) & 1, jb + 1);
        CP_COMMIT();
        const int buf = jb & 1;

        // ---- S = Q @ K^T (log2e*scale pre-folded into Q) ----
        float sc[8][4];
#pragma unroll
        for (int nb = 0; nb < 8; ++nb)
#pragma unroll
            for (int i = 0; i < 4; ++i) sc[nb][i] = 0.0f;

#pragma unroll
        for (int kc = 0; kc < 8; ++kc) {
#pragma unroll
            for (int nt = 0; nt < 4; ++nt) {
                uint32_t k0, k1, k2, k3;
                LDSM_X4(k0, k1, k2, k3,
                        s2u(&Ks[buf][nt * 16 + l15][kc * 16 + l16]));
                MMA16816(sc[nt * 2],     qa[kc][0], qa[kc][1], qa[kc][2], qa[kc][3], k0, k2);
                MMA16816(sc[nt * 2 + 1], qa[kc][0], qa[kc][1], qa[kc][2], qa[kc][3], k1, k3);
            }
        }

        // ---- mask + row max (fp32) ----
        const bool needmask = (jb * 64 + 63 > warp_row0);
        float mn[2], alpha[2];
#pragma unroll
        for (int rr = 0; rr < 2; ++rr) {
            const int rowg = warp_row0 + g + rr * 8;
            float tm = -1e30f;
#pragma unroll
            for (int nb = 0; nb < 8; ++nb) {
                float s0 = sc[nb][rr * 2], s1 = sc[nb][rr * 2 + 1];
                if (needmask) {
                    const int colg = jb * 64 + nb * 8 + c;
                    if (colg > rowg)     s0 = -1e30f;
                    if (colg + 1 > rowg) s1 = -1e30f;
                    sc[nb][rr * 2] = s0; sc[nb][rr * 2 + 1] = s1;
                }
                tm = fmaxf(tm, fmaxf(s0, s1));
            }
            tm = fmaxf(tm, __shfl_xor_sync(0xffffffffu, tm, 1));
            tm = fmaxf(tm, __shfl_xor_sync(0xffffffffu, tm, 2));
            mn[rr] = fmaxf(m_[rr], tm);
            alpha[rr] = exp2f(m_[rr] - mn[rr]);
            m_[rr] = mn[rr];
        }

        // ---- p = 2^(s-m) in fp16x2; outputs are PV A-fragments directly ----
        uint32_t pa[4][4];
        float sum0 = 0.0f, sum1 = 0.0f;
#pragma unroll
        for (int nb = 0; nb < 8; ++nb) {
            __half2 e0 = h2exp2(__floats2half2_rn(sc[nb][0] - mn[0],
                                                  sc[nb][1] - mn[0]));
            __half2 e1 = h2exp2(__floats2half2_rn(sc[nb][2] - mn[1],
                                                  sc[nb][3] - mn[1]));
            pa[nb >> 1][(nb & 1) ? 2 : 0] = *(uint32_t*)&e0;
            pa[nb >> 1][(nb & 1) ? 3 : 1] = *(uint32_t*)&e1;
            float2 f0 = __half22float2(e0);
            float2 f1 = __half22float2(e1);
            sum0 += f0.x + f0.y;
            sum1 += f1.x + f1.y;
        }
        sum0 += __shfl_xor_sync(0xffffffffu, sum0, 1);
        sum0 += __shfl_xor_sync(0xffffffffu, sum0, 2);
        sum1 += __shfl_xor_sync(0xffffffffu, sum1, 1);
        sum1 += __shfl_xor_sync(0xffffffffu, sum1, 2);
        l_[0] = l_[0] * alpha[0] + sum0;
        l_[1] = l_[1] * alpha[1] + sum1;
#pragma unroll
        for (int nb = 0; nb < 16; ++nb) {
            of[nb][0] *= alpha[0];
            of[nb][1] *= alpha[0];
            of[nb][2] *= alpha[1];
            of[nb][3] *= alpha[1];
        }

        // ---- O += P @ V ----
#pragma unroll
        for (int k2 = 0; k2 < 4; ++k2) {
#pragma unroll
            for (int nt = 0; nt < 8; ++nt) {
                uint32_t v0, v1, v2, v3;
                LDSM_X4T(v0, v1, v2, v3,
                         s2u(&Vs[buf][k2 * 16 + l15][nt * 16 + l16]));
                MMA16816(of[nt * 2],     pa[k2][0], pa[k2][1], pa[k2][2], pa[k2][3], v0, v1);
                MMA16816(of[nt * 2 + 1], pa[k2][0], pa[k2][1], pa[k2][2], pa[k2][3], v2, v3);
            }
        }

        CP_WAIT0();   // next KV tile landed (overlapped with compute above)
    }

    // epilogue: normalize, write half
    const float inv0 = 1.0f / l_[0];
    const float inv1 = 1.0f / l_[1];
    const size_t row = (size_t)(b * NS + qb * 128 + w * 16 + g);
#pragma unroll
    for (int nb = 0; nb < 16; ++nb) {
        const int col = h * NDH + nb * 8 + c;
        *(__half2*)&g_oh[row * ND + col] =
            __floats2half2_rn(of[nb][0] * inv0, of[nb][1] * inv0);
        *(__half2*)&g_oh[(row + 8) * ND + col] =
            __floats2half2_rn(of[nb][2] * inv1, of[nb][3] * inv1);
    }
}

// ---------------------------------------------------------------------------
extern "C" void kernel_launch(void* const* d_in, const int* in_sizes, int n_in,
                              void* d_out, int out_size)
{
    const float* x  = (const float*)d_in[0];
    const float* fc = (const float*)d_in[1];
    const float* fs = (const float*)d_in[2];
    const float* wq = (const float*)d_in[3];
    const float* wk = (const float*)d_in[4];
    const float* wv = (const float*)d_in[5];
    const float* wo = (const float*)d_in[6];
    float* out = (float*)d_out;

    __half *xh, *wqkvh, *woh, *qkvh, *oh;
    cudaGetSymbolAddress((void**)&xh,    g_xh);
    cudaGetSymbolAddress((void**)&wqkvh, g_wqkvh);
    cudaGetSymbolAddress((void**)&woh,   g_woh);
    cudaGetSymbolAddress((void**)&qkvh,  g_qkvh);
    cudaGetSymbolAddress((void**)&oh,    g_oh);

    // fp32 -> fp16 conversions: x (launch 1), all weights (launch 2)
    const int nx = NROWS * ND / 4;
    const int nw_total = 2 * (ND * ND / 4) + 2 * ((NKVH * NDH) * ND / 4);
    f2h_kernel<<<(nx + 255) / 256, 256>>>(x, xh, nx);
    f2h_w_kernel<<<(nw_total + 255) / 256, 256>>>(wq, wk, wv, wo);

    // Fused QKV projection + RoPE epilogue:
    // [4096,2048] @ [3072,2048]^T -> [4096,3072] half, rope on q/k cols
    cudaFuncSetAttribute(hgemm_nt<2>,
                         cudaFuncAttributeMaxDynamicSharedMemorySize, GEMM_SMEM);
    cudaFuncSetAttribute(hgemm_nt<0>,
                         cudaFuncAttributeMaxDynamicSharedMemorySize, GEMM_SMEM);
    hgemm_nt<2><<<dim3(NQKV / 128, NROWS / 128), 128, GEMM_SMEM>>>(
        xh, wqkvh, qkvh, NROWS, NQKV, ND, fc, fs);

    // Causal GQA flash attention
    cudaFuncSetAttribute(attn_h_kernel,
                         cudaFuncAttributeMaxDynamicSharedMemorySize, ATTN_SMEM);
    attn_h_kernel<<<dim3(NS / 128, NH, NB), 256, ATTN_SMEM>>>();

    // Output projection (fp32 output)
    hgemm_nt<0><<<dim3(ND / 128, NROWS / 128), 128, GEMM_SMEM>>>(
        oh, woh, out, NROWS, ND, ND, nullptr, nullptr);
}

// round 14
// speedup vs baseline: 1.1082x; 1.0416x over previous
#include <cuda_runtime.h>
#include <cuda_fp16.h>
#include <cstdint>

// Problem constants
#define NB    2
#define NS    2048
#define ND    2048
#define NH    16
#define NKVH  4
#define NDH   128
#define NROWS (NB * NS)        // 4096
#define NQKV  3072             // 2048 q + 512 k + 512 v

// fp16 scratch (static device globals: allocation-free)
__device__ __half g_xh   [(size_t)NROWS * ND];    // 16 MB
__device__ __half g_wqkvh[(size_t)NQKV * ND];     // 12 MB  (wq | wk | wv rows)
__device__ __half g_woh  [(size_t)ND * ND];       //  8 MB
__device__ __half g_qkvh [(size_t)NROWS * NQKV];  // 24 MB  row: [q 2048 | k 512 | v 512]
__device__ __half g_oh   [(size_t)NROWS * ND];    // 16 MB

// ---------------------------------------------------------------------------
// PTX helpers
// ---------------------------------------------------------------------------
#define MMA16816(d, a0, a1, a2, a3, b0, b1)                                  \
    asm volatile(                                                            \
        "mma.sync.aligned.m16n8k16.row.col.f32.f16.f16.f32 "                 \
        "{%0,%1,%2,%3}, {%4,%5,%6,%7}, {%8,%9}, {%0,%1,%2,%3};"              \
        : "+f"((d)[0]), "+f"((d)[1]), "+f"((d)[2]), "+f"((d)[3])             \
        : "r"(a0), "r"(a1), "r"(a2), "r"(a3), "r"(b0), "r"(b1))

#define CP_ASYNC16(dst, src)                                                 \
    asm volatile("cp.async.cg.shared.global [%0], [%1], 16;" ::              \
                 "r"(dst), "l"(src))
#define CP_COMMIT() asm volatile("cp.async.commit_group;")
#define CP_WAIT0()  asm volatile("cp.async.wait_group 0;" ::: "memory")
#define CP_WAIT1()  asm volatile("cp.async.wait_group 1;" ::: "memory")

#define LDSM_X4(r0, r1, r2, r3, a)                                           \
    asm volatile("ldmatrix.sync.aligned.m8n8.x4.shared.b16 "                 \
                 "{%0,%1,%2,%3}, [%4];"                                      \
                 : "=r"(r0), "=r"(r1), "=r"(r2), "=r"(r3) : "r"(a))
#define LDSM_X4T(r0, r1, r2, r3, a)                                          \
    asm volatile("ldmatrix.sync.aligned.m8n8.x4.trans.shared.b16 "           \
                 "{%0,%1,%2,%3}, [%4];"                                      \
                 : "=r"(r0), "=r"(r1), "=r"(r2), "=r"(r3) : "r"(a))

__device__ __forceinline__ uint32_t s2u(const void* p) {
    return (uint32_t)__cvta_generic_to_shared(p);
}

// ---------------------------------------------------------------------------
// float -> half conversions
// ---------------------------------------------------------------------------
__global__ void f2h_kernel(const float* __restrict__ in, __half* __restrict__ out,
                           int n4)
{
    int i = blockIdx.x * blockDim.x + threadIdx.x;
    if (i < n4) {
        float4 v = ((const float4*)in)[i];
        __half2* o = (__half2*)out + i * 2;
        o[0] = __floats2half2_rn(v.x, v.y);
        o[1] = __floats2half2_rn(v.z, v.w);
    }
}

__global__ void f2h_w_kernel(const float* __restrict__ wq,
                             const float* __restrict__ wk,
                             const float* __restrict__ wv,
                             const float* __restrict__ wo)
{
    const int NWQ = ND * ND / 4;            // 1048576 float4 groups
    const int NKV = (NKVH * NDH) * ND / 4;  // 262144
    int i = blockIdx.x * blockDim.x + threadIdx.x;

    const float* src;
    __half* dst;
    int off;
    if (i < NWQ) {
        src = wq; dst = g_wqkvh; off = i;
    } else if (i < NWQ + NKV) {
        src = wk; dst = g_wqkvh + (size_t)2048 * 2048; off = i - NWQ;
    } else if (i < NWQ + 2 * NKV) {
        src = wv; dst = g_wqkvh + (size_t)2560 * 2048; off = i - NWQ - NKV;
    } else if (i < 2 * NWQ + 2 * NKV) {
        src = wo; dst = g_woh; off = i - NWQ - 2 * NKV;
    } else {
        return;
    }
    float4 v = ((const float4*)src)[off];
    __half2* o = (__half2*)dst + off * 2;
    o[0] = __floats2half2_rn(v.x, v.y);
    o[1] = __floats2half2_rn(v.z, v.w);
}

// ---------------------------------------------------------------------------
// HGEMM: C[M,N] = A[M,K](half,row) @ W[N,K](half,row)^T, fp32 accum.
// CTA tile 128x128, BK=32, 128 threads (4 warps, warp tile 64x64),
// 3-stage cp.async ring, ldmatrix fragment loads.
// MODE: 0 = fp32 out, 1 = half out, 2 = half out + fused RoPE epilogue
// ---------------------------------------------------------------------------
#define SKP 40
#define GEMM_SMEM (2 * 3 * 128 * SKP * 2)   // 61440 B

template <int MODE>
__global__ __launch_bounds__(128)
void hgemm_nt(const __half* __restrict__ A, const __half* __restrict__ W,
              void* __restrict__ Cout, int M, int N, int K,
              const float* __restrict__ fc, const float* __restrict__ fs)
{
    extern __shared__ __half hsm[];
    __half (*As)[128][SKP] = (__half(*)[128][SKP])hsm;
    __half (*Bs)[128][SKP] = (__half(*)[128][SKP])(hsm + 3 * 128 * SKP);

    const int m0 = blockIdx.y * 128;
    const int n0 = blockIdx.x * 128;
    const int t  = threadIdx.x;
    const int lane = t & 31, wid = t >> 5;
    const int wm = (wid & 1) * 64;
    const int wn = (wid >> 1) * 64;
    const int g  = lane >> 2;
    const int c  = (lane & 3) * 2;
    const int l15 = lane & 15, l16 = (lane >> 4) * 8;

    float acc[4][8][4];
#pragma unroll
    for (int mt = 0; mt < 4; ++mt)
#pragma unroll
        for (int nb = 0; nb < 8; ++nb)
#pragma unroll
            for (int i = 0; i < 4; ++i) acc[mt][nb][i] = 0.0f;

    const int lr = t >> 2, lseg = (t & 3) * 8;

    auto load_tile = [&](int buf, int k0) {
#pragma unroll
        for (int it = 0; it < 4; ++it) {
            const int row = lr + it * 32;
            CP_ASYNC16(s2u(&As[buf][row][lseg]),
                       A + (size_t)(m0 + row) * K + k0 + lseg);
            CP_ASYNC16(s2u(&Bs[buf][row][lseg]),
                       W + (size_t)(n0 + row) * K + k0 + lseg);
        }
    };

    const int NSTG = K / 32;
    load_tile(0, 0);  CP_COMMIT();
    load_tile(1, 32); CP_COMMIT();

    for (int s = 0; s < NSTG; ++s) {
        CP_WAIT1();
        __syncthreads();
        if (s + 2 < NSTG) load_tile((s + 2) % 3, (s + 2) * 32);
        CP_COMMIT();
        const int buf = s % 3;

#pragma unroll
        for (int kc = 0; kc < 32; kc += 16) {
            uint32_t a[4][4], b[4][4];
#pragma unroll
            for (int mt = 0; mt < 4; ++mt)
                LDSM_X4(a[mt][0], a[mt][1], a[mt][2], a[mt][3],
                        s2u(&As[buf][wm + mt * 16 + l15][kc + l16]));
#pragma unroll
            for (int nt = 0; nt < 4; ++nt)
                LDSM_X4(b[nt][0], b[nt][1], b[nt][2], b[nt][3],
                        s2u(&Bs[buf][wn + nt * 16 + l15][kc + l16]));
            // b[nt][0]=b0(n), b[nt][1]=b0(n+8), b[nt][2]=b1(n), b[nt][3]=b1(n+8)
#pragma unroll
            for (int mt = 0; mt < 4; ++mt)
#pragma unroll
                for (int nb = 0; nb < 8; ++nb)
                    MMA16816(acc[mt][nb],
                             a[mt][0], a[mt][1], a[mt][2], a[mt][3],
                             b[nb >> 1][nb & 1], b[nb >> 1][2 + (nb & 1)]);
        }
    }

    // epilogue
#pragma unroll
    for (int mt = 0; mt < 4; ++mt) {
#pragma unroll
        for (int nb = 0; nb < 8; ++nb) {
            const size_t row = (size_t)(m0 + wm + mt * 16 + g);
            const int col = n0 + wn + nb * 8 + c;
            if (MODE == 2 && col < 2560) {
                const int pi = (col & (NDH - 1)) >> 1;
                const int s0 = (int)(row & (NS - 1));
                const int s1 = (int)((row + 8) & (NS - 1));
                const float c0 = fc[s0 * 64 + pi], sn0 = fs[s0 * 64 + pi];
                const float c1 = fc[s1 * 64 + pi], sn1 = fs[s1 * 64 + pi];
                float r0 = acc[mt][nb][0] * c0 - acc[mt][nb][1] * sn0;
                float i0 = acc[mt][nb][0] * sn0 + acc[mt][nb][1] * c0;
                float r1 = acc[mt][nb][2] * c1 - acc[mt][nb][3] * sn1;
                float i1 = acc[mt][nb][2] * sn1 + acc[mt][nb][3] * c1;
                if (col < 2048) {
                    const float qsc = 0.08838834764831845f * 1.4426950408889634f;
                    r0 *= qsc; i0 *= qsc; r1 *= qsc; i1 *= qsc;
                }
                acc[mt][nb][0] = r0; acc[mt][nb][1] = i0;
                acc[mt][nb][2] = r1; acc[mt][nb][3] = i1;
            }
            if (MODE != 0) {
                __half* C = (__half*)Cout;
                *(__half2*)&C[row * N + col] =
                    __floats2half2_rn(acc[mt][nb][0], acc[mt][nb][1]);
                *(__half2*)&C[(row + 8) * N + col] =
                    __floats2half2_rn(acc[mt][nb][2], acc[mt][nb][3]);
            } else {
                float* C = (float*)Cout;
                *(float2*)&C[row * N + col] =
                    make_float2(acc[mt][nb][0], acc[mt][nb][1]);
                *(float2*)&C[(row + 8) * N + col] =
                    make_float2(acc[mt][nb][2], acc[mt][nb][3]);
            }
        }
    }
}

// ---------------------------------------------------------------------------
// Flash attention: 64 q-rows x 64 kv-cols per CTA, 4 warps (128 threads),
// Dh=128. 2 CTAs/SM (regs 45.6K, smem 174KB) -> two independent barrier
// domains per SM so one CTA's MMAs hide the other's softmax tail.
// Q fragments hoisted; K/V via ldmatrix (trans for V); cp.async
// double-buffered KV tiles; base-2 fp16x2 softmax.
// ---------------------------------------------------------------------------
#define VP 136
#define ATTN_SMEM ((64 + 4 * 64) * VP * 2)   // 87040 B

__global__ __launch_bounds__(128)
void attn_h_kernel()
{
    extern __shared__ __half sm[];
    __half (*Qs)[VP]     = (__half(*)[VP])sm;                      // [64][VP]
    __half (*Ks)[64][VP] = (__half(*)[64][VP])(sm + 64 * VP);      // [2][64][VP]
    __half (*Vs)[64][VP] = (__half(*)[64][VP])(sm + 192 * VP);     // [2][64][VP]

    const int qb = (int)gridDim.x - 1 - (int)blockIdx.x;  // big tiles first
    const int h  = blockIdx.y;
    const int b  = blockIdx.z;
    const int kvh = h >> 2;

    const int t = threadIdx.x;
    const int lane = t & 31, w = t >> 5;
    const int g = lane >> 2;
    const int c = (lane & 3) * 2;
    const int l15 = lane & 15, l16 = (lane >> 4) * 8;

    const __half* qkv = g_qkvh;

    auto load_kv = [&](int buf, int jb) {
#pragma unroll
        for (int it = 0; it < 8; ++it) {
            const int i = t + it * 128;
            const int row = i >> 4, seg = (i & 15) * 8;
            const size_t grow = (size_t)(b * NS + jb * 64 + row) * NQKV + kvh * NDH + seg;
            CP_ASYNC16(s2u(&Ks[buf][row][seg]), qkv + grow + 2048);
            CP_ASYNC16(s2u(&Vs[buf][row][seg]), qkv + grow + 2560);
        }
    };

    // Q tile (64 rows, head h) + first KV tile
#pragma unroll
    for (int it = 0; it < 8; ++it) {
        const int i = t + it * 128;
        const int row = i >> 4, seg = (i & 15) * 8;
        CP_ASYNC16(s2u(&Qs[row][seg]),
                   qkv + (size_t)(b * NS + qb * 64 + row) * NQKV + h * NDH + seg);
    }
    load_kv(0, 0);
    CP_COMMIT();
    CP_WAIT0();
    __syncthreads();

    // Hoist Q fragments (loop-invariant)
    uint32_t qa[8][4];
#pragma unroll
    for (int kc = 0; kc < 8; ++kc)
        LDSM_X4(qa[kc][0], qa[kc][1], qa[kc][2], qa[kc][3],
                s2u(&Qs[w * 16 + l15][kc * 16 + l16]));

    float of[16][4];
#pragma unroll
    for (int nb = 0; nb < 16; ++nb)
#pragma unroll
        for (int i = 0; i < 4; ++i) of[nb][i] = 0.0f;
    float m_[2] = {-1e30f, -1e30f};
    float l_[2] = {0.0f, 0.0f};

    const int jmax = qb;
    const int warp_row0 = qb * 64 + w * 16;

    for (int jb = 0; jb <= jmax; ++jb) {
        __syncthreads();   // all warps done with buf (jb-1)&1; buf jb published
        if (jb + 1 <= jmax) load_kv((jb + 1) & 1, jb + 1);
        CP_COMMIT();
        const int buf = jb & 1;

        // ---- S = Q @ K^T (log2e*scale pre-folded into Q) ----
        float sc[8][4];
#pragma unroll
        for (int nb = 0; nb < 8; ++nb)
#pragma unroll
            for (int i = 0; i < 4; ++i) sc[nb][i] = 0.0f;

#pragma unroll
        for (int kc = 0; kc < 8; ++kc) {
#pragma unroll
            for (int nt = 0; nt < 4; ++nt) {
                uint32_t k0, k1, k2, k3;
                LDSM_X4(k0, k1, k2, k3,
                        s2u(&Ks[buf][nt * 16 + l15][kc * 16 + l16]));
                MMA16816(sc[nt * 2],     qa[kc][0], qa[kc][1], qa[kc][2], qa[kc][3], k0, k2);
                MMA16816(sc[nt * 2 + 1], qa[kc][0], qa[kc][1], qa[kc][2], qa[kc][3], k1, k3);
            }
        }

        // ---- mask + row max (fp32) ----
        const bool needmask = (jb * 64 + 63 > warp_row0);
        float mn[2], alpha[2];
#pragma unroll
        for (int rr = 0; rr < 2; ++rr) {
            const int rowg = warp_row0 + g + rr * 8;
            float tm = -1e30f;
#pragma unroll
            for (int nb = 0; nb < 8; ++nb) {
                float s0 = sc[nb][rr * 2], s1 = sc[nb][rr * 2 + 1];
                if (needmask) {
                    const int colg = jb * 64 + nb * 8 + c;
                    if (colg > rowg)     s0 = -1e30f;
                    if (colg + 1 > rowg) s1 = -1e30f;
                    sc[nb][rr * 2] = s0; sc[nb][rr * 2 + 1] = s1;
                }
                tm = fmaxf(tm, fmaxf(s0, s1));
            }
            tm = fmaxf(tm, __shfl_xor_sync(0xffffffffu, tm, 1));
            tm = fmaxf(tm, __shfl_xor_sync(0xffffffffu, tm, 2));
            mn[rr] = fmaxf(m_[rr], tm);
            alpha[rr] = exp2f(m_[rr] - mn[rr]);
            m_[rr] = mn[rr];
        }

        // ---- p = 2^(s-m) in fp16x2; outputs are PV A-fragments directly ----
        uint32_t pa[4][4];
        float sum0 = 0.0f, sum1 = 0.0f;
#pragma unroll
        for (int nb = 0; nb < 8; ++nb) {
            __half2 e0 = h2exp2(__floats2half2_rn(sc[nb][0] - mn[0],
                                                  sc[nb][1] - mn[0]));
            __half2 e1 = h2exp2(__floats2half2_rn(sc[nb][2] - mn[1],
                                                  sc[nb][3] - mn[1]));
            pa[nb >> 1][(nb & 1) ? 2 : 0] = *(uint32_t*)&e0;
            pa[nb >> 1][(nb & 1) ? 3 : 1] = *(uint32_t*)&e1;
            float2 f0 = __half22float2(e0);
            float2 f1 = __half22float2(e1);
            sum0 += f0.x + f0.y;
            sum1 += f1.x + f1.y;
        }
        sum0 += __shfl_xor_sync(0xffffffffu, sum0, 1);
        sum0 += __shfl_xor_sync(0xffffffffu, sum0, 2);
        sum1 += __shfl_xor_sync(0xffffffffu, sum1, 1);
        sum1 += __shfl_xor_sync(0xffffffffu, sum1, 2);
        l_[0] = l_[0] * alpha[0] + sum0;
        l_[1] = l_[1] * alpha[1] + sum1;
#pragma unroll
        for (int nb = 0; nb < 16; ++nb) {
            of[nb][0] *= alpha[0];
            of[nb][1] *= alpha[0];
            of[nb][2] *= alpha[1];
            of[nb][3] *= alpha[1];
        }

        // ---- O += P @ V ----
#pragma unroll
        for (int k2 = 0; k2 < 4; ++k2) {
#pragma unroll
            for (int nt = 0; nt < 8; ++nt) {
                uint32_t v0, v1, v2, v3;
                LDSM_X4T(v0, v1, v2, v3,
                         s2u(&Vs[buf][k2 * 16 + l15][nt * 16 + l16]));
                MMA16816(of[nt * 2],     pa[k2][0], pa[k2][1], pa[k2][2], pa[k2][3], v0, v1);
                MMA16816(of[nt * 2 + 1], pa[k2][0], pa[k2][1], pa[k2][2], pa[k2][3], v2, v3);
            }
        }

        CP_WAIT0();   // next KV tile landed (overlapped with compute above)
    }

    // epilogue: normalize, write half
    const float inv0 = 1.0f / l_[0];
    const float inv1 = 1.0f / l_[1];
    const size_t row = (size_t)(b * NS + qb * 64 + w * 16 + g);
#pragma unroll
    for (int nb = 0; nb < 16; ++nb) {
        const int col = h * NDH + nb * 8 + c;
        *(__half2*)&g_oh[row * ND + col] =
            __floats2half2_rn(of[nb][0] * inv0, of[nb][1] * inv0);
        *(__half2*)&g_oh[(row + 8) * ND + col] =
            __floats2half2_rn(of[nb][2] * inv1, of[nb][3] * inv1);
    }
}

// ---------------------------------------------------------------------------
extern "C" void kernel_launch(void* const* d_in, const int* in_sizes, int n_in,
                              void* d_out, int out_size)
{
    const float* x  = (const float*)d_in[0];
    const float* fc = (const float*)d_in[1];
    const float* fs = (const float*)d_in[2];
    const float* wq = (const float*)d_in[3];
    const float* wk = (const float*)d_in[4];
    const float* wv = (const float*)d_in[5];
    const float* wo = (const float*)d_in[6];
    float* out = (float*)d_out;

    __half *xh, *wqkvh, *woh, *qkvh, *oh;
    cudaGetSymbolAddress((void**)&xh,    g_xh);
    cudaGetSymbolAddress((void**)&wqkvh, g_wqkvh);
    cudaGetSymbolAddress((void**)&woh,   g_woh);
    cudaGetSymbolAddress((void**)&qkvh,  g_qkvh);
    cudaGetSymbolAddress((void**)&oh,    g_oh);

    // fp32 -> fp16 conversions: x (launch 1), all weights (launch 2)
    const int nx = NROWS * ND / 4;
    const int nw_total = 2 * (ND * ND / 4) + 2 * ((NKVH * NDH) * ND / 4);
    f2h_kernel<<<(nx + 255) / 256, 256>>>(x, xh, nx);
    f2h_w_kernel<<<(nw_total + 255) / 256, 256>>>(wq, wk, wv, wo);

    // Fused QKV projection + RoPE epilogue:
    // [4096,2048] @ [3072,2048]^T -> [4096,3072] half, rope on q/k cols
    cudaFuncSetAttribute(hgemm_nt<2>,
                         cudaFuncAttributeMaxDynamicSharedMemorySize, GEMM_SMEM);
    cudaFuncSetAttribute(hgemm_nt<0>,
                         cudaFuncAttributeMaxDynamicSharedMemorySize, GEMM_SMEM);
    hgemm_nt<2><<<dim3(NQKV / 128, NROWS / 128), 128, GEMM_SMEM>>>(
        xh, wqkvh, qkvh, NROWS, NQKV, ND, fc, fs);

    // Causal GQA flash attention: 64-row q tiles, 2 CTAs/SM
    cudaFuncSetAttribute(attn_h_kernel,
                         cudaFuncAttributeMaxDynamicSharedMemorySize, ATTN_SMEM);
    attn_h_kernel<<<dim3(NS / 64, NH, NB), 128, ATTN_SMEM>>>();

    // Output projection (fp32 output)
    hgemm_nt<0><<<dim3(ND / 128, NROWS / 128), 128, GEMM_SMEM>>>(
        oh, woh, out, NROWS, ND, ND, nullptr, nullptr);
}

// round 15
// speedup vs baseline: 1.1371x; 1.0261x over previous
#include <cuda_runtime.h>
#include <cuda_fp16.h>
#include <cstdint>

// Problem constants
#define NB    2
#define NS    2048
#define ND    2048
#define NH    16
#define NKVH  4
#define NDH   128
#define NROWS (NB * NS)        // 4096
#define NQKV  3072             // 2048 q + 512 k + 512 v

// fp16 scratch (static device globals: allocation-free)
__device__ __half g_xh   [(size_t)NROWS * ND];    // 16 MB
__device__ __half g_wqkvh[(size_t)NQKV * ND];     // 12 MB  (wq | wk | wv rows)
__device__ __half g_woh  [(size_t)ND * ND];       //  8 MB
__device__ __half g_qkvh [(size_t)NROWS * NQKV];  // 24 MB  row: [q 2048 | k 512 | v 512]
__device__ __half g_oh   [(size_t)NROWS * ND];    // 16 MB

// ---------------------------------------------------------------------------
// PTX helpers
// ---------------------------------------------------------------------------
#define MMA16816(d, a0, a1, a2, a3, b0, b1)                                  \
    asm volatile(                                                            \
        "mma.sync.aligned.m16n8k16.row.col.f32.f16.f16.f32 "                 \
        "{%0,%1,%2,%3}, {%4,%5,%6,%7}, {%8,%9}, {%0,%1,%2,%3};"              \
        : "+f"((d)[0]), "+f"((d)[1]), "+f"((d)[2]), "+f"((d)[3])             \
        : "r"(a0), "r"(a1), "r"(a2), "r"(a3), "r"(b0), "r"(b1))

#define CP_ASYNC16(dst, src)                                                 \
    asm volatile("cp.async.cg.shared.global [%0], [%1], 16;" ::              \
                 "r"(dst), "l"(src))
#define CP_COMMIT() asm volatile("cp.async.commit_group;")
#define CP_WAIT0()  asm volatile("cp.async.wait_group 0;" ::: "memory")
#define CP_WAIT1()  asm volatile("cp.async.wait_group 1;" ::: "memory")

#define LDSM_X4(r0, r1, r2, r3, a)                                           \
    asm volatile("ldmatrix.sync.aligned.m8n8.x4.shared.b16 "                 \
                 "{%0,%1,%2,%3}, [%4];"                                      \
                 : "=r"(r0), "=r"(r1), "=r"(r2), "=r"(r3) : "r"(a))
#define LDSM_X4T(r0, r1, r2, r3, a)                                          \
    asm volatile("ldmatrix.sync.aligned.m8n8.x4.trans.shared.b16 "           \
                 "{%0,%1,%2,%3}, [%4];"                                      \
                 : "=r"(r0), "=r"(r1), "=r"(r2), "=r"(r3) : "r"(a))

__device__ __forceinline__ uint32_t s2u(const void* p) {
    return (uint32_t)__cvta_generic_to_shared(p);
}

// ---------------------------------------------------------------------------
// float -> half conversions
// ---------------------------------------------------------------------------
__global__ void f2h_kernel(const float* __restrict__ in, __half* __restrict__ out,
                           int n4)
{
    int i = blockIdx.x * blockDim.x + threadIdx.x;
    if (i < n4) {
        float4 v = ((const float4*)in)[i];
        __half2* o = (__half2*)out + i * 2;
        o[0] = __floats2half2_rn(v.x, v.y);
        o[1] = __floats2half2_rn(v.z, v.w);
    }
}

__global__ void f2h_w_kernel(const float* __restrict__ wq,
                             const float* __restrict__ wk,
                             const float* __restrict__ wv,
                             const float* __restrict__ wo)
{
    const int NWQ = ND * ND / 4;            // 1048576 float4 groups
    const int NKV = (NKVH * NDH) * ND / 4;  // 262144
    int i = blockIdx.x * blockDim.x + threadIdx.x;

    const float* src;
    __half* dst;
    int off;
    if (i < NWQ) {
        src = wq; dst = g_wqkvh; off = i;
    } else if (i < NWQ + NKV) {
        src = wk; dst = g_wqkvh + (size_t)2048 * 2048; off = i - NWQ;
    } else if (i < NWQ + 2 * NKV) {
        src = wv; dst = g_wqkvh + (size_t)2560 * 2048; off = i - NWQ - NKV;
    } else if (i < 2 * NWQ + 2 * NKV) {
        src = wo; dst = g_woh; off = i - NWQ - 2 * NKV;
    } else {
        return;
    }
    float4 v = ((const float4*)src)[off];
    __half2* o = (__half2*)dst + off * 2;
    o[0] = __floats2half2_rn(v.x, v.y);
    o[1] = __floats2half2_rn(v.z, v.w);
}

// ---------------------------------------------------------------------------
// HGEMM: C[M,N] = A[M,K](half,row) @ W[N,K](half,row)^T, fp32 accum.
// CTA tile 128x128, BK=32, 128 threads (4 warps, warp tile 64x64),
// 3-stage cp.async ring, ldmatrix fragment loads.
// MODE: 0 = fp32 out, 1 = half out, 2 = half out + fused RoPE epilogue
// ---------------------------------------------------------------------------
#define SKP 40
#define GEMM_SMEM (2 * 3 * 128 * SKP * 2)   // 61440 B

template <int MODE>
__global__ __launch_bounds__(128)
void hgemm_nt(const __half* __restrict__ A, const __half* __restrict__ W,
              void* __restrict__ Cout, int M, int N, int K,
              const float* __restrict__ fc, const float* __restrict__ fs)
{
    extern __shared__ __half hsm[];
    __half (*As)[128][SKP] = (__half(*)[128][SKP])hsm;
    __half (*Bs)[128][SKP] = (__half(*)[128][SKP])(hsm + 3 * 128 * SKP);

    const int m0 = blockIdx.y * 128;
    const int n0 = blockIdx.x * 128;
    const int t  = threadIdx.x;
    const int lane = t & 31, wid = t >> 5;
    const int wm = (wid & 1) * 64;
    const int wn = (wid >> 1) * 64;
    const int g  = lane >> 2;
    const int c  = (lane & 3) * 2;
    const int l15 = lane & 15, l16 = (lane >> 4) * 8;

    float acc[4][8][4];
#pragma unroll
    for (int mt = 0; mt < 4; ++mt)
#pragma unroll
        for (int nb = 0; nb < 8; ++nb)
#pragma unroll
            for (int i = 0; i < 4; ++i) acc[mt][nb][i] = 0.0f;

    const int lr = t >> 2, lseg = (t & 3) * 8;

    auto load_tile = [&](int buf, int k0) {
#pragma unroll
        for (int it = 0; it < 4; ++it) {
            const int row = lr + it * 32;
            CP_ASYNC16(s2u(&As[buf][row][lseg]),
                       A + (size_t)(m0 + row) * K + k0 + lseg);
            CP_ASYNC16(s2u(&Bs[buf][row][lseg]),
                       W + (size_t)(n0 + row) * K + k0 + lseg);
        }
    };

    const int NSTG = K / 32;
    load_tile(0, 0);  CP_COMMIT();
    load_tile(1, 32); CP_COMMIT();

    for (int s = 0; s < NSTG; ++s) {
        CP_WAIT1();
        __syncthreads();
        if (s + 2 < NSTG) load_tile((s + 2) % 3, (s + 2) * 32);
        CP_COMMIT();
        const int buf = s % 3;

#pragma unroll
        for (int kc = 0; kc < 32; kc += 16) {
            uint32_t a[4][4], b[4][4];
#pragma unroll
            for (int mt = 0; mt < 4; ++mt)
                LDSM_X4(a[mt][0], a[mt][1], a[mt][2], a[mt][3],
                        s2u(&As[buf][wm + mt * 16 + l15][kc + l16]));
#pragma unroll
            for (int nt = 0; nt < 4; ++nt)
                LDSM_X4(b[nt][0], b[nt][1], b[nt][2], b[nt][3],
                        s2u(&Bs[buf][wn + nt * 16 + l15][kc + l16]));
            // b[nt][0]=b0(n), b[nt][1]=b0(n+8), b[nt][2]=b1(n), b[nt][3]=b1(n+8)
#pragma unroll
            for (int mt = 0; mt < 4; ++mt)
#pragma unroll
                for (int nb = 0; nb < 8; ++nb)
                    MMA16816(acc[mt][nb],
                             a[mt][0], a[mt][1], a[mt][2], a[mt][3],
                             b[nb >> 1][nb & 1], b[nb >> 1][2 + (nb & 1)]);
        }
    }

    // epilogue
#pragma unroll
    for (int mt = 0; mt < 4; ++mt) {
#pragma unroll
        for (int nb = 0; nb < 8; ++nb) {
            const size_t row = (size_t)(m0 + wm + mt * 16 + g);
            const int col = n0 + wn + nb * 8 + c;
            if (MODE == 2 && col < 2560) {
                const int pi = (col & (NDH - 1)) >> 1;
                const int s0 = (int)(row & (NS - 1));
                const int s1 = (int)((row + 8) & (NS - 1));
                const float c0 = fc[s0 * 64 + pi], sn0 = fs[s0 * 64 + pi];
                const float c1 = fc[s1 * 64 + pi], sn1 = fs[s1 * 64 + pi];
                float r0 = acc[mt][nb][0] * c0 - acc[mt][nb][1] * sn0;
                float i0 = acc[mt][nb][0] * sn0 + acc[mt][nb][1] * c0;
                float r1 = acc[mt][nb][2] * c1 - acc[mt][nb][3] * sn1;
                float i1 = acc[mt][nb][2] * sn1 + acc[mt][nb][3] * c1;
                if (col < 2048) {
                    const float qsc = 0.08838834764831845f * 1.4426950408889634f;
                    r0 *= qsc; i0 *= qsc; r1 *= qsc; i1 *= qsc;
                }
                acc[mt][nb][0] = r0; acc[mt][nb][1] = i0;
                acc[mt][nb][2] = r1; acc[mt][nb][3] = i1;
            }
            if (MODE != 0) {
                __half* C = (__half*)Cout;
                *(__half2*)&C[row * N + col] =
                    __floats2half2_rn(acc[mt][nb][0], acc[mt][nb][1]);
                *(__half2*)&C[(row + 8) * N + col] =
                    __floats2half2_rn(acc[mt][nb][2], acc[mt][nb][3]);
            } else {
                float* C = (float*)Cout;
                *(float2*)&C[row * N + col] =
                    make_float2(acc[mt][nb][0], acc[mt][nb][1]);
                *(float2*)&C[(row + 8) * N + col] =
                    make_float2(acc[mt][nb][2], acc[mt][nb][3]);
            }
        }
    }
}

// ---------------------------------------------------------------------------
// Flash attention: 64 q-rows x 64 kv-cols per CTA, 4 warps (128 threads).
// Q is STAGED through the K-buffer smem region (dead after fragment hoist),
// so smem/CTA = 68 KB -> 3 CTAs/SM (12 warps, 3 barrier domains).
// K/V via ldmatrix (trans for V); cp.async double-buffered KV tiles;
// base-2 fp16x2 softmax.
// ---------------------------------------------------------------------------
#define VP 136
#define ATTN_SMEM (256 * VP * 2)   // 69632 B: [2][64][VP] K + [2][64][VP] V

__global__ __launch_bounds__(128, 3)
void attn_h_kernel()
{
    extern __shared__ __half sm[];
    __half (*Ks)[64][VP] = (__half(*)[64][VP])sm;                  // [2][64][VP]
    __half (*Vs)[64][VP] = (__half(*)[64][VP])(sm + 128 * VP);     // [2][64][VP]
    __half* Qstage = sm;   // aliases Ks ring; valid only in prologue

    const int qb = (int)gridDim.x - 1 - (int)blockIdx.x;  // big tiles first
    const int h  = blockIdx.y;
    const int b  = blockIdx.z;
    const int kvh = h >> 2;

    const int t = threadIdx.x;
    const int lane = t & 31, w = t >> 5;
    const int g = lane >> 2;
    const int c = (lane & 3) * 2;
    const int l15 = lane & 15, l16 = (lane >> 4) * 8;

    const __half* qkv = g_qkvh;

    auto load_kv = [&](int buf, int jb) {
#pragma unroll
        for (int it = 0; it < 8; ++it) {
            const int i = t + it * 128;
            const int row = i >> 4, seg = (i & 15) * 8;
            const size_t grow = (size_t)(b * NS + jb * 64 + row) * NQKV + kvh * NDH + seg;
            CP_ASYNC16(s2u(&Ks[buf][row][seg]), qkv + grow + 2048);
            CP_ASYNC16(s2u(&Vs[buf][row][seg]), qkv + grow + 2560);
        }
    };

    // ---- Prologue: stage Q through the K ring, hoist fragments ----
#pragma unroll
    for (int it = 0; it < 8; ++it) {
        const int i = t + it * 128;
        const int row = i >> 4, seg = (i & 15) * 8;
        CP_ASYNC16(s2u(Qstage + row * VP + seg),
                   qkv + (size_t)(b * NS + qb * 64 + row) * NQKV + h * NDH + seg);
    }
    CP_COMMIT();
    CP_WAIT0();
    __syncthreads();

    uint32_t qa[8][4];
#pragma unroll
    for (int kc = 0; kc < 8; ++kc)
        LDSM_X4(qa[kc][0], qa[kc][1], qa[kc][2], qa[kc][3],
                s2u(Qstage + (w * 16 + l15) * VP + kc * 16 + l16));

    __syncthreads();   // all warps done reading Q staging before K0 overwrites

    load_kv(0, 0);
    CP_COMMIT();
    CP_WAIT0();

    float of[16][4];
#pragma unroll
    for (int nb = 0; nb < 16; ++nb)
#pragma unroll
        for (int i = 0; i < 4; ++i) of[nb][i] = 0.0f;
    float m_[2] = {-1e30f, -1e30f};
    float l_[2] = {0.0f, 0.0f};

    const int jmax = qb;
    const int warp_row0 = qb * 64 + w * 16;

    for (int jb = 0; jb <= jmax; ++jb) {
        __syncthreads();   // all warps done with buf (jb-1)&1; buf jb published
        if (jb + 1 <= jmax) load_kv((jb + 1) & 1, jb + 1);
        CP_COMMIT();
        const int buf = jb & 1;

        // ---- S = Q @ K^T (log2e*scale pre-folded into Q) ----
        float sc[8][4];
#pragma unroll
        for (int nb = 0; nb < 8; ++nb)
#pragma unroll
            for (int i = 0; i < 4; ++i) sc[nb][i] = 0.0f;

#pragma unroll
        for (int kc = 0; kc < 8; ++kc) {
#pragma unroll
            for (int nt = 0; nt < 4; ++nt) {
                uint32_t k0, k1, k2, k3;
                LDSM_X4(k0, k1, k2, k3,
                        s2u(&Ks[buf][nt * 16 + l15][kc * 16 + l16]));
                MMA16816(sc[nt * 2],     qa[kc][0], qa[kc][1], qa[kc][2], qa[kc][3], k0, k2);
                MMA16816(sc[nt * 2 + 1], qa[kc][0], qa[kc][1], qa[kc][2], qa[kc][3], k1, k3);
            }
        }

        // ---- mask + row max (fp32) ----
        const bool needmask = (jb * 64 + 63 > warp_row0);
        float mn[2], alpha[2];
#pragma unroll
        for (int rr = 0; rr < 2; ++rr) {
            const int rowg = warp_row0 + g + rr * 8;
            float tm = -1e30f;
#pragma unroll
            for (int nb = 0; nb < 8; ++nb) {
                float s0 = sc[nb][rr * 2], s1 = sc[nb][rr * 2 + 1];
                if (needmask) {
                    const int colg = jb * 64 + nb * 8 + c;
                    if (colg > rowg)     s0 = -1e30f;
                    if (colg + 1 > rowg) s1 = -1e30f;
                    sc[nb][rr * 2] = s0; sc[nb][rr * 2 + 1] = s1;
                }
                tm = fmaxf(tm, fmaxf(s0, s1));
            }
            tm = fmaxf(tm, __shfl_xor_sync(0xffffffffu, tm, 1));
            tm = fmaxf(tm, __shfl_xor_sync(0xffffffffu, tm, 2));
            mn[rr] = fmaxf(m_[rr], tm);
            alpha[rr] = exp2f(m_[rr] - mn[rr]);
            m_[rr] = mn[rr];
        }

        // ---- p = 2^(s-m) in fp16x2; outputs are PV A-fragments directly ----
        uint32_t pa[4][4];
        float sum0 = 0.0f, sum1 = 0.0f;
#pragma unroll
        for (int nb = 0; nb < 8; ++nb) {
            __half2 e0 = h2exp2(__floats2half2_rn(sc[nb][0] - mn[0],
                                                  sc[nb][1] - mn[0]));
            __half2 e1 = h2exp2(__floats2half2_rn(sc[nb][2] - mn[1],
                                                  sc[nb][3] - mn[1]));
            pa[nb >> 1][(nb & 1) ? 2 : 0] = *(uint32_t*)&e0;
            pa[nb >> 1][(nb & 1) ? 3 : 1] = *(uint32_t*)&e1;
            float2 f0 = __half22float2(e0);
            float2 f1 = __half22float2(e1);
            sum0 += f0.x + f0.y;
            sum1 += f1.x + f1.y;
        }
        sum0 += __shfl_xor_sync(0xffffffffu, sum0, 1);
        sum0 += __shfl_xor_sync(0xffffffffu, sum0, 2);
        sum1 += __shfl_xor_sync(0xffffffffu, sum1, 1);
        sum1 += __shfl_xor_sync(0xffffffffu, sum1, 2);
        l_[0] = l_[0] * alpha[0] + sum0;
        l_[1] = l_[1] * alpha[1] + sum1;
#pragma unroll
        for (int nb = 0; nb < 16; ++nb) {
            of[nb][0] *= alpha[0];
            of[nb][1] *= alpha[0];
            of[nb][2] *= alpha[1];
            of[nb][3] *= alpha[1];
        }

        // ---- O += P @ V ----
#pragma unroll
        for (int k2 = 0; k2 < 4; ++k2) {
#pragma unroll
            for (int nt = 0; nt < 8; ++nt) {
                uint32_t v0, v1, v2, v3;
                LDSM_X4T(v0, v1, v2, v3,
                         s2u(&Vs[buf][k2 * 16 + l15][nt * 16 + l16]));
                MMA16816(of[nt * 2],     pa[k2][0], pa[k2][1], pa[k2][2], pa[k2][3], v0, v1);
                MMA16816(of[nt * 2 + 1], pa[k2][0], pa[k2][1], pa[k2][2], pa[k2][3], v2, v3);
            }
        }

        CP_WAIT0();   // next KV tile landed (overlapped with compute above)
    }

    // epilogue: normalize, write half
    const float inv0 = 1.0f / l_[0];
    const float inv1 = 1.0f / l_[1];
    const size_t row = (size_t)(b * NS + qb * 64 + w * 16 + g);
#pragma unroll
    for (int nb = 0; nb < 16; ++nb) {
        const int col = h * NDH + nb * 8 + c;
        *(__half2*)&g_oh[row * ND + col] =
            __floats2half2_rn(of[nb][0] * inv0, of[nb][1] * inv0);
        *(__half2*)&g_oh[(row + 8) * ND + col] =
            __floats2half2_rn(of[nb][2] * inv1, of[nb][3] * inv1);
    }
}

// ---------------------------------------------------------------------------
extern "C" void kernel_launch(void* const* d_in, const int* in_sizes, int n_in,
                              void* d_out, int out_size)
{
    const float* x  = (const float*)d_in[0];
    const float* fc = (const float*)d_in[1];
    const float* fs = (const float*)d_in[2];
    const float* wq = (const float*)d_in[3];
    const float* wk = (const float*)d_in[4];
    const float* wv = (const float*)d_in[5];
    const float* wo = (const float*)d_in[6];
    float* out = (float*)d_out;

    __half *xh, *wqkvh, *woh, *qkvh, *oh;
    cudaGetSymbolAddress((void**)&xh,    g_xh);
    cudaGetSymbolAddress((void**)&wqkvh, g_wqkvh);
    cudaGetSymbolAddress((void**)&woh,   g_woh);
    cudaGetSymbolAddress((void**)&qkvh,  g_qkvh);
    cudaGetSymbolAddress((void**)&oh,    g_oh);

    // fp32 -> fp16 conversions: x (launch 1), all weights (launch 2)
    const int nx = NROWS * ND / 4;
    const int nw_total = 2 * (ND * ND / 4) + 2 * ((NKVH * NDH) * ND / 4);
    f2h_kernel<<<(nx + 255) / 256, 256>>>(x, xh, nx);
    f2h_w_kernel<<<(nw_total + 255) / 256, 256>>>(wq, wk, wv, wo);

    // Fused QKV projection + RoPE epilogue:
    // [4096,2048] @ [3072,2048]^T -> [4096,3072] half, rope on q/k cols
    cudaFuncSetAttribute(hgemm_nt<2>,
                         cudaFuncAttributeMaxDynamicSharedMemorySize, GEMM_SMEM);
    cudaFuncSetAttribute(hgemm_nt<0>,
                         cudaFuncAttributeMaxDynamicSharedMemorySize, GEMM_SMEM);
    hgemm_nt<2><<<dim3(NQKV / 128, NROWS / 128), 128, GEMM_SMEM>>>(
        xh, wqkvh, qkvh, NROWS, NQKV, ND, fc, fs);

    // Causal GQA flash attention: 64-row q tiles, Q staged via KV smem,
    // 3 CTAs/SM
    cudaFuncSetAttribute(attn_h_kernel,
                         cudaFuncAttributeMaxDynamicSharedMemorySize, ATTN_SMEM);
    attn_h_kernel<<<dim3(NS / 64, NH, NB), 128, ATTN_SMEM>>>();

    // Output projection (fp32 output)
    hgemm_nt<0><<<dim3(ND / 128, NROWS / 128), 128, GEMM_SMEM>>>(
        oh, woh, out, NROWS, ND, ND, nullptr, nullptr);
}